// round 11
// baseline (speedup 1.0000x reference)
#include <cuda_runtime.h>
#include <cuda_fp16.h>
#include <cstdint>

// ---------------------------------------------------------------------------
// Problem constants
// ---------------------------------------------------------------------------
#define NROWS   50000
#define F_IN    768
#define PROJ    1024
#define HID     256
#define OUTD    128
#define NR ((size_t)NROWS)
#define EMAX_TOT 900000

// ---------------------------------------------------------------------------
// Arena of static device scratch (no runtime allocation allowed)
// ---------------------------------------------------------------------------
constexpr size_t OFF_AXH   = 0;                                   // half [NR x 768]
constexpr size_t OFF_CXH   = OFF_AXH + NR * F_IN * 2;             // half [NR x 768]
constexpr size_t OFF_A12H  = OFF_CXH + NR * F_IN * 2;             // half [NR x 512]
constexpr size_t OFF_CCH   = OFF_A12H + NR * 512 * 2;             // half [NR x 512]
constexpr size_t OFF_H1RH  = OFF_CCH + NR * 512 * 2;              // half [NR x 256]
constexpr size_t OFF_TH    = OFF_H1RH + NR * HID * 2;             // half [NR x 256]
constexpr size_t OFF_H1H   = OFF_TH + NR * HID * 2;
constexpr size_t OFF_H2H   = OFF_H1H + NR * HID * 2;
constexpr size_t OFF_H3H   = OFF_H2H + NR * HID * 2;
constexpr size_t OFF_W1H   = OFF_H3H + NR * HID * 2;              // half [768 x 1024]
constexpr size_t OFF_W2H   = OFF_W1H + (size_t)F_IN * PROJ * 2;
constexpr size_t OFF_WL1T  = OFF_W2H + (size_t)F_IN * PROJ * 2;   // half [256 x 1024]
constexpr size_t OFF_WL2T  = OFF_WL1T + (size_t)HID * PROJ * 2;   // contiguous after WL1T!
constexpr size_t OFF_WR1T  = OFF_WL2T + (size_t)HID * PROJ * 2;
constexpr size_t OFF_WAT   = OFF_WR1T + (size_t)HID * PROJ * 2;   // half [512 x 768]
constexpr size_t OFF_WCT   = OFF_WAT + (size_t)512 * F_IN * 2;    // half [512 x 768]
constexpr size_t OFF_WR2T  = OFF_WCT + (size_t)512 * F_IN * 2;    // half [256 x 256]
constexpr size_t OFF_WL3T  = OFF_WR2T + (size_t)HID * HID * 2;
constexpr size_t OFF_W3T   = OFF_WL3T + (size_t)HID * HID * 2;    // half [128 x 256]
constexpr size_t OFF_BA    = OFF_W3T + (size_t)OUTD * HID * 2;    // fp32 [512]
constexpr size_t OFF_BC    = OFF_BA + 512 * 4;                    // fp32 [512]
constexpr size_t OFF_CNT   = OFF_BC + 512 * 4;                    // int [3 x 50000]
constexpr size_t OFF_ROWST = OFF_CNT + 3 * NR * 4;                // int [3 x 50001]
constexpr size_t OFF_CURSOR= OFF_ROWST + 3 * (NR + 1) * 4;        // int [3 x 50000]
constexpr size_t OFF_CSR   = OFF_CURSOR + 3 * NR * 4;             // int [900000]
constexpr size_t ARENA_TOTAL = OFF_CSR + (size_t)EMAX_TOT * 4 + 64;

__device__ unsigned char g_arena[ARENA_TOTAL];

__device__ __forceinline__ uint32_t smem_u32(const void* p) {
    uint32_t a;
    asm("{ .reg .u64 t; cvta.to.shared.u64 t, %1; cvt.u32.u64 %0, t; }" : "=r"(a) : "l"(p));
    return a;
}

// ---------------------------------------------------------------------------
// Batched tensor-core GEMM via mma.sync:
//   C[M,N] = A[M,K](fp16) @ B[N,K](fp16)^T (+bias), fp32 accumulate.
// Tile 128x128x32, 8 warps (4Mx2N), 4-stage cp.async pipeline (3-deep
// prefetch: covers ~1500 cyc of DRAM latency at 16 warps/SM occupancy).
// GRID ORDER: blockIdx.x = N-block (fastest) so CTAs sharing an A row-tile
// are bid-adjacent -> same wave -> A tile read once from DRAM, rest L2 hits.
// blockIdx.z selects one of two independent jobs (batched launch).
// smem rows padded to 40 halfs (80B stride -> conflict-free ldmatrix).
// Requires: N % 128 == 0, K % 32 == 0. M arbitrary.
// ---------------------------------------------------------------------------
#define GM 128
#define GN 128
#define GK 32
#define SROW 40
#define STAGES 4
#define ABYTES (GM * SROW * 2)            // 10240
#define STAGE_BYTES (2 * ABYTES)          // A + B per stage
#define GEMM_SMEM (STAGES * STAGE_BYTES)  // 81920

struct GemmJob {
    const __half* A;
    const __half* B;
    void* C;
    const float* bias;
    int M;
    int ldc;
};

template<bool HALF_OUT>
__global__ void __launch_bounds__(256, 2)
mma_gemm_kernel(GemmJob j0, GemmJob j1, int K)
{
    const GemmJob j = (blockIdx.z == 0) ? j0 : j1;
    const int m0 = blockIdx.y * GM;           // M on y (slow axis)
    if (m0 >= j.M) return;
    const int n0 = blockIdx.x * GN;           // N on x (fast axis -> L2 reuse of A)

    extern __shared__ __align__(16) char dynsmem[];
    const uint32_t sbase = smem_u32(dynsmem);

    const int tid = threadIdx.x;
    const int lane = tid & 31, wid = tid >> 5;
    const int warp_m = wid >> 1, warp_n = wid & 1;
    const int nk = K / GK;

    float acc[2][8][4];
#pragma unroll
    for (int i = 0; i < 2; i++)
#pragma unroll
        for (int jj = 0; jj < 8; jj++)
#pragma unroll
            for (int q = 0; q < 4; q++) acc[i][jj][q] = 0.f;

    auto issue = [&](int ch) {
        int st = ch % STAGES;
        int k0 = ch * GK;
        uint32_t baseA = sbase + st * STAGE_BYTES;
        uint32_t baseB = baseA + ABYTES;
#pragma unroll
        for (int i = 0; i < 2; i++) {
            int idx = tid + i * 256;          // 0..511
            int row = idx >> 2;               // 0..127
            int c8  = (idx & 3) << 3;         // 0,8,16,24
            uint32_t soff = (uint32_t)(row * SROW + c8) * 2;
            int gr = m0 + row;
            const __half* ga = j.A + (size_t)(gr < j.M ? gr : 0) * K + k0 + c8;
            int sz = (gr < j.M) ? 16 : 0;
            asm volatile("cp.async.cg.shared.global [%0], [%1], 16, %2;"
                         :: "r"(baseA + soff), "l"(ga), "r"(sz));
            const __half* gb = j.B + (size_t)(n0 + row) * K + k0 + c8;
            asm volatile("cp.async.cg.shared.global [%0], [%1], 16;"
                         :: "r"(baseB + soff), "l"(gb));
        }
        asm volatile("cp.async.commit_group;");
    };

    // 3-deep prefetch prologue
    issue(0);
    if (nk > 1) issue(1);
    if (nk > 2) issue(2);

    for (int ch = 0; ch < nk; ch++) {
        // wait for stage ch: keep at most (inflight-1) groups pending
        if (ch + 2 < nk)      asm volatile("cp.async.wait_group 2;");
        else if (ch + 1 < nk) asm volatile("cp.async.wait_group 1;");
        else                  asm volatile("cp.async.wait_group 0;");
        __syncthreads();
        if (ch + 3 < nk) issue(ch + 3);

        int st = ch % STAGES;
        uint32_t baseA = sbase + st * STAGE_BYTES;
        uint32_t baseB = baseA + ABYTES;
#pragma unroll
        for (int ks = 0; ks < 2; ks++) {
            int kk = ks * 16;
            uint32_t a[2][4];
#pragma unroll
            for (int wm = 0; wm < 2; wm++) {
                int row = warp_m * 32 + wm * 16 + (lane & 15);
                int col = kk + ((lane >> 4) << 3);
                uint32_t addr = baseA + (uint32_t)(row * SROW + col) * 2;
                asm volatile("ldmatrix.sync.aligned.m8n8.x4.shared.b16 {%0,%1,%2,%3}, [%4];"
                             : "=r"(a[wm][0]), "=r"(a[wm][1]), "=r"(a[wm][2]), "=r"(a[wm][3])
                             : "r"(addr));
            }
            uint32_t b[8][2];
#pragma unroll
            for (int p = 0; p < 4; p++) {
                int n = warp_n * 64 + p * 16 + (lane & 7) + ((lane >> 4) << 3);
                int col = kk + (((lane >> 3) & 1) << 3);
                uint32_t addr = baseB + (uint32_t)(n * SROW + col) * 2;
                uint32_t r0, r1, r2, r3;
                asm volatile("ldmatrix.sync.aligned.m8n8.x4.shared.b16 {%0,%1,%2,%3}, [%4];"
                             : "=r"(r0), "=r"(r1), "=r"(r2), "=r"(r3) : "r"(addr));
                b[2 * p][0] = r0; b[2 * p][1] = r1;
                b[2 * p + 1][0] = r2; b[2 * p + 1][1] = r3;
            }
#pragma unroll
            for (int wm = 0; wm < 2; wm++)
#pragma unroll
                for (int wn = 0; wn < 8; wn++)
                    asm volatile(
                        "mma.sync.aligned.m16n8k16.row.col.f32.f16.f16.f32 "
                        "{%0,%1,%2,%3}, {%4,%5,%6,%7}, {%8,%9}, {%0,%1,%2,%3};"
                        : "+f"(acc[wm][wn][0]), "+f"(acc[wm][wn][1]),
                          "+f"(acc[wm][wn][2]), "+f"(acc[wm][wn][3])
                        : "r"(a[wm][0]), "r"(a[wm][1]), "r"(a[wm][2]), "r"(a[wm][3]),
                          "r"(b[wn][0]), "r"(b[wn][1]));
        }
        __syncthreads();
    }

    // Epilogue
    float* Cf = (float*)j.C;
    __half* Ch = (__half*)j.C;
#pragma unroll
    for (int wm = 0; wm < 2; wm++) {
        int r = m0 + warp_m * 32 + wm * 16 + (lane >> 2);
#pragma unroll
        for (int wn = 0; wn < 8; wn++) {
            int c = n0 + warp_n * 64 + wn * 8 + ((lane & 3) << 1);
            float b0 = 0.f, b1 = 0.f;
            if (j.bias) { b0 = j.bias[c]; b1 = j.bias[c + 1]; }
            if (r < j.M) {
                float v0 = acc[wm][wn][0] + b0, v1 = acc[wm][wn][1] + b1;
                if (HALF_OUT)
                    *(__half2*)(Ch + (size_t)r * j.ldc + c) = __floats2half2_rn(v0, v1);
                else
                    *(float2*)(Cf + (size_t)r * j.ldc + c) = make_float2(v0, v1);
            }
            if (r + 8 < j.M) {
                float v0 = acc[wm][wn][2] + b0, v1 = acc[wm][wn][3] + b1;
                if (HALF_OUT)
                    *(__half2*)(Ch + (size_t)(r + 8) * j.ldc + c) = __floats2half2_rn(v0, v1);
                else
                    *(float2*)(Cf + (size_t)(r + 8) * j.ldc + c) = make_float2(v0, v1);
            }
        }
    }
}

// ---------------------------------------------------------------------------
// Dual fp32->fp16 conversion (two tensors, one launch)
// ---------------------------------------------------------------------------
__global__ void tohalf2_kernel(const float4* __restrict__ x0, __half2* __restrict__ o0,
                               const float4* __restrict__ x1, __half2* __restrict__ o1,
                               int n4)
{
    int i = blockIdx.x * blockDim.x + threadIdx.x;
    const float4* x; __half2* o; int j;
    if (i < n4)          { x = x0; o = o0; j = i; }
    else if (i < 2 * n4) { x = x1; o = o1; j = i - n4; }
    else return;
    float4 v = x[j];
    o[2 * j]     = __floats2half2_rn(v.x, v.y);
    o[2 * j + 1] = __floats2half2_rn(v.z, v.w);
}

// ---------------------------------------------------------------------------
// Batched prep: 7 transposes (fp32 [KxN] -> fp16 [NxK]) + 3 bias folds + zero
// ---------------------------------------------------------------------------
__device__ __forceinline__ void tjob(const float* __restrict__ W, __half* __restrict__ T,
                                     int K, int N, int local)
{
    int k = local / N, n = local % N;
    T[(size_t)n * K + k] = __float2half(W[local]);
}
__device__ __forceinline__ void vjob(const float* __restrict__ b, const float* __restrict__ W,
                                     float* __restrict__ out, int K, int c)
{
    float a0 = 0.f, a1 = 0.f, a2 = 0.f, a3 = 0.f;
    for (int k = 0; k < K; k += 4) {
        a0 += b[k]     * W[(size_t)k * 256 + c];
        a1 += b[k + 1] * W[(size_t)(k + 1) * 256 + c];
        a2 += b[k + 2] * W[(size_t)(k + 2) * 256 + c];
        a3 += b[k + 3] * W[(size_t)(k + 3) * 256 + c];
    }
    out[c] = (a0 + a1) + (a2 + a3);
}

#define TBLOCKS 4480   // 1146880 / 256

__global__ void prep_kernel(
    const float* Wl1, const float* Wl2, const float* Wr1,
    const float* Wr2, const float* Wl3, const float* W3, const float* Wr3,
    __half* Wl1t, __half* Wl2t, __half* Wr1t,
    __half* Wr2t, __half* Wl3t, __half* W3t, __half* Wr3t,
    const float* b1, const float* b2, float* bA, float* bC)
{
    int blk = blockIdx.x;
    if (blk < TBLOCKS) {
        int t = blk * 256 + threadIdx.x;
        if      (t <  262144) tjob(Wl1, Wl1t, 1024, 256, t);
        else if (t <  524288) tjob(Wl2, Wl2t, 1024, 256, t - 262144);
        else if (t <  786432) tjob(Wr1, Wr1t, 1024, 256, t - 524288);
        else if (t <  851968) tjob(Wr2, Wr2t,  256, 256, t - 786432);
        else if (t <  917504) tjob(Wl3, Wl3t,  256, 256, t - 851968);
        else if (t <  950272) tjob(W3,  W3t,   256, 128, t - 917504);
        else                  tjob(Wr3, Wr3t,  768, 256, t - 950272);
    } else {
        int which = blk - TBLOCKS;
        int c = threadIdx.x;
        if (which == 0) vjob(b1, Wl1, bA, 1024, c);
        else if (which == 1) vjob(b1, Wl2, bA + 256, 1024, c);
        else { vjob(b2, Wr1, bC, 1024, c); bC[256 + c] = 0.f; }
    }
}

// ---------------------------------------------------------------------------
// CSR build for all 3 graphs, batched
// ---------------------------------------------------------------------------
__global__ void count3_kernel(const int* __restrict__ e0, int E0,
                              const int* __restrict__ e1, int E1,
                              const int* __restrict__ e2, int E2,
                              int* __restrict__ cnt)
{
    int t = blockIdx.x * blockDim.x + threadIdx.x;
    if (t < E0)                atomicAdd(&cnt[e0[E0 + t]], 1);
    else if (t < E0 + E1)      atomicAdd(&cnt[NROWS + e1[E1 + (t - E0)]], 1);
    else if (t < E0 + E1 + E2) atomicAdd(&cnt[2 * NROWS + e2[E2 + (t - E0 - E1)]], 1);
}

__global__ void scan3_kernel(const int* __restrict__ cnt,
                             int* __restrict__ rowstart, int* __restrict__ cursor)
{
    __shared__ int warp_sums[32];
    __shared__ int s_carry;
    int g = blockIdx.x;
    const int* c = cnt + (size_t)g * NROWS;
    int* rs = rowstart + (size_t)g * (NROWS + 1);
    int* cu = cursor + (size_t)g * NROWS;
    int tid = threadIdx.x, lane = tid & 31, wid = tid >> 5;
    if (tid == 0) s_carry = 0;
    __syncthreads();
    for (int base = 0; base < NROWS; base += 1024) {
        int i = base + tid;
        int v = (i < NROWS) ? c[i] : 0;
        int x = v;
#pragma unroll
        for (int off = 1; off < 32; off <<= 1) {
            int y = __shfl_up_sync(0xffffffffu, x, off);
            if (lane >= off) x += y;
        }
        if (lane == 31) warp_sums[wid] = x;
        __syncthreads();
        if (wid == 0) {
            int w = warp_sums[lane];
#pragma unroll
            for (int off = 1; off < 32; off <<= 1) {
                int y = __shfl_up_sync(0xffffffffu, w, off);
                if (lane >= off) w += y;
            }
            warp_sums[lane] = w;
        }
        __syncthreads();
        int warp_off = (wid > 0) ? warp_sums[wid - 1] : 0;
        int incl = x + warp_off;
        int carry = s_carry;
        if (i < NROWS) { int ex = carry + incl - v; rs[i] = ex; cu[i] = ex; }
        __syncthreads();
        if (tid == 1023) s_carry = carry + incl;
        __syncthreads();
    }
    if (tid == 0) rs[NROWS] = s_carry;
}

__global__ void fill3_kernel(const int* __restrict__ e0, int E0,
                             const int* __restrict__ e1, int E1,
                             const int* __restrict__ e2, int E2,
                             int* __restrict__ cursor, int* __restrict__ csr)
{
    int t = blockIdx.x * blockDim.x + threadIdx.x;
    if (t < E0) {
        int p = atomicAdd(&cursor[e0[E0 + t]], 1);
        csr[p] = e0[t];
    } else if (t < E0 + E1) {
        int j = t - E0;
        int p = atomicAdd(&cursor[NROWS + e1[E1 + j]], 1);
        csr[E0 + p] = e1[j];
    } else if (t < E0 + E1 + E2) {
        int j = t - E0 - E1;
        int p = atomicAdd(&cursor[2 * NROWS + e2[E2 + j]], 1);
        csr[E0 + E1 + p] = e2[j];
    }
}

// ---------------------------------------------------------------------------
// Fused mean-aggregate + bias + residual + ReLU (half2 wide, unroll-4 MLP)
// out(r,:) = relu( mean_{s in row r} S[s,:] + bias + other[r,:] ), fp16 in/out
// ---------------------------------------------------------------------------
__global__ void __launch_bounds__(128)
aggregate_kernel(const int* __restrict__ rowstart, const int* __restrict__ csr,
                 const __half2* __restrict__ S2, int ldS2,
                 const __half2* __restrict__ other2, int ldO2,
                 const float* __restrict__ bias,
                 __half2* __restrict__ out2)
{
    int r = blockIdx.x;
    int c2 = threadIdx.x;
    int s = rowstart[r], e = rowstart[r + 1];
    float ax = 0.f, ay = 0.f, bx = 0.f, by = 0.f;
    int i = s;
    for (; i + 4 <= e; i += 4) {
        int i0 = csr[i], i1 = csr[i + 1], i2 = csr[i + 2], i3 = csr[i + 3];
        float2 v0 = __half22float2(S2[(size_t)i0 * ldS2 + c2]);
        float2 v1 = __half22float2(S2[(size_t)i1 * ldS2 + c2]);
        float2 v2 = __half22float2(S2[(size_t)i2 * ldS2 + c2]);
        float2 v3 = __half22float2(S2[(size_t)i3 * ldS2 + c2]);
        ax += v0.x + v1.x; ay += v0.y + v1.y;
        bx += v2.x + v3.x; by += v2.y + v3.y;
    }
    for (; i < e; i++) {
        float2 v = __half22float2(S2[(size_t)csr[i] * ldS2 + c2]);
        ax += v.x; ay += v.y;
    }
    float inv = 1.f / fmaxf((float)(e - s), 1.f);
    float2 oth = __half22float2(other2[(size_t)r * ldO2 + c2]);
    float bb0 = bias[2 * c2], bb1 = bias[2 * c2 + 1];
    float vx = fmaxf((ax + bx) * inv + bb0 + oth.x, 0.f);
    float vy = fmaxf((ay + by) * inv + bb1 + oth.y, 0.f);
    out2[(size_t)r * 128 + c2] = __floats2half2_rn(vx, vy);
}

// ---------------------------------------------------------------------------
// Host helpers  (grid: x = N-blocks [fast], y = M-blocks, z = job)
// ---------------------------------------------------------------------------
static inline void gemm1_f16(int M, int N, int K, const __half* A, const __half* B,
                             __half* C, int ldc, const float* bias)
{
    GemmJob j{A, B, (void*)C, bias, M, ldc};
    dim3 g(N / GN, (M + GM - 1) / GM, 1);
    mma_gemm_kernel<true><<<g, 256, GEMM_SMEM>>>(j, j, K);
}

extern "C" void kernel_launch(void* const* d_in, const int* in_sizes, int n_in,
                              void* d_out, int out_size)
{
    const float* article_x   = (const float*)d_in[0];
    const float* community_x = (const float*)d_in[1];
    const int*   e_wb        = (const int*)d_in[2];
    const int*   e_mb        = (const int*)d_in[3];
    const int*   e_int       = (const int*)d_in[4];
    const float* W1  = (const float*)d_in[5];
    const float* b1  = (const float*)d_in[6];
    const float* W2  = (const float*)d_in[7];
    const float* b2  = (const float*)d_in[8];
    const float* Wl1 = (const float*)d_in[9];
    const float* bl1 = (const float*)d_in[10];
    const float* Wr1 = (const float*)d_in[11];
    const float* Wl2 = (const float*)d_in[12];
    const float* bl2 = (const float*)d_in[13];
    const float* Wr2 = (const float*)d_in[14];
    const float* Wl3 = (const float*)d_in[15];
    const float* bl3 = (const float*)d_in[16];
    const float* Wr3 = (const float*)d_in[17];
    const float* W3  = (const float*)d_in[18];
    const float* b3  = (const float*)d_in[19];

    const int E0 = in_sizes[2] / 2;   // e_wb
    const int E1 = in_sizes[3] / 2;   // e_mb
    const int E2 = in_sizes[4] / 2;   // e_int

    cudaFuncSetAttribute(mma_gemm_kernel<true>,
                         cudaFuncAttributeMaxDynamicSharedMemorySize, GEMM_SMEM);
    cudaFuncSetAttribute(mma_gemm_kernel<false>,
                         cudaFuncAttributeMaxDynamicSharedMemorySize, GEMM_SMEM);

    unsigned char* arena;
    cudaGetSymbolAddress((void**)&arena, g_arena);
#define AP(T, off) ((T*)(arena + (off)))
    __half *AxH  = AP(__half, OFF_AXH),  *CxH  = AP(__half, OFF_CXH);
    __half *A12H = AP(__half, OFF_A12H), *CCH  = AP(__half, OFF_CCH);
    __half *h1rH = AP(__half, OFF_H1RH), *tH   = AP(__half, OFF_TH);
    __half *h1H  = AP(__half, OFF_H1H), *h2H = AP(__half, OFF_H2H), *h3H = AP(__half, OFF_H3H);
    __half *W1H  = AP(__half, OFF_W1H), *W2H = AP(__half, OFF_W2H);
    __half *Wl1t = AP(__half, OFF_WL1T), *Wl2t = AP(__half, OFF_WL2T), *Wr1t = AP(__half, OFF_WR1T);
    __half *WAt  = AP(__half, OFF_WAT),  *WCt  = AP(__half, OFF_WCT);
    __half *Wr2t = AP(__half, OFF_WR2T), *Wl3t = AP(__half, OFF_WL3T), *W3t = AP(__half, OFF_W3T);
    float  *bA   = AP(float, OFF_BA),    *bC   = AP(float, OFF_BC);
    int *cnt = AP(int, OFF_CNT), *rowstart = AP(int, OFF_ROWST);
    int *cursor = AP(int, OFF_CURSOR), *csr = AP(int, OFF_CSR);

    // [1] W1,W2 -> fp16
    {
        int n4 = F_IN * PROJ / 4;
        tohalf2_kernel<<<(2 * n4 + 255) / 256, 256>>>(
            (const float4*)W1, (__half2*)W1H, (const float4*)W2, (__half2*)W2H, n4);
    }
    // [2] all transposes + bias folds + bC zero
    prep_kernel<<<TBLOCKS + 3, 256>>>(Wl1, Wl2, Wr1, Wr2, Wl3, W3, Wr3,
                                      Wl1t, Wl2t, Wr1t, Wr2t, Wl3t, W3t,
                                      WCt + (size_t)256 * F_IN,
                                      b1, b2, bA, bC);
    // [3] BOTH weight folds in one batched launch (z=2)
    //   z0: WAt[512,768] = [Wl1t;Wl2t] @ W1H^T    z1: WCt[0:256] = Wr1t @ W2H^T
    {
        GemmJob ja{Wl1t, W1H, (void*)WAt, nullptr, 512, F_IN};
        GemmJob jc{Wr1t, W2H, (void*)WCt, nullptr, HID, F_IN};
        dim3 g(F_IN / GN, 512 / GM, 2);
        mma_gemm_kernel<true><<<g, 256, GEMM_SMEM>>>(ja, jc, PROJ);
    }
    // [4] activations -> fp16
    {
        int n4 = (int)(NR * F_IN / 4);
        tohalf2_kernel<<<(2 * n4 + 255) / 256, 256>>>(
            (const float4*)article_x, (__half2*)AxH,
            (const float4*)community_x, (__half2*)CxH, n4);
    }
    // [5] BOTH big projections in one batched launch (z=2), fp16 outputs
    //   z0: A12H = article_x @ [W1Wl1|W1Wl2] + bA    z1: CCH = community_x @ [W2Wr1|Wr3] + bC
    {
        GemmJob ja{AxH, WAt, (void*)A12H, bA, NROWS, 512};
        GemmJob jc{CxH, WCt, (void*)CCH, bC, NROWS, 512};
        dim3 g(512 / GN, (NROWS + GM - 1) / GM, 2);
        mma_gemm_kernel<true><<<g, 256, GEMM_SMEM>>>(ja, jc, F_IN);
    }

    // [6-9] CSR build for all three graphs
    cudaMemsetAsync(cnt, 0, 3 * NROWS * sizeof(int));
    {
        int Etot = E0 + E1 + E2;
        count3_kernel<<<(Etot + 255) / 256, 256>>>(e_wb, E0, e_mb, E1, e_int, E2, cnt);
        scan3_kernel<<<3, 1024>>>(cnt, rowstart, cursor);
        fill3_kernel<<<(Etot + 255) / 256, 256>>>(e_wb, E0, e_mb, E1, e_int, E2, cursor, csr);
    }

    // [10] conv1: h1 = relu(mean(A1[src]) + bl1 + C1)
    aggregate_kernel<<<NROWS, 128>>>(rowstart, csr,
                                     (const __half2*)A12H, 256,
                                     (const __half2*)CCH, 256, bl1, (__half2*)h1H);
    // [11] h1r = h1 @ Wr2  (fp16)
    gemm1_f16(NROWS, HID, HID, h1H, Wr2t, h1rH, HID, nullptr);
    // [12] conv2: h2 = relu(mean(A2[src]) + bl2 + h1r)
    aggregate_kernel<<<NROWS, 128>>>(rowstart + (NROWS + 1), csr + E0,
                                     (const __half2*)(A12H + HID), 256,
                                     (const __half2*)h1rH, 128, bl2, (__half2*)h2H);
    // [13] t = h2 @ Wl3 (fp16: gather source)
    gemm1_f16(NROWS, HID, HID, h2H, Wl3t, tH, HID, nullptr);
    // [14] conv3: h3 = relu(mean(t[src]) + bl3 + CC[:,256:512])
    aggregate_kernel<<<NROWS, 128>>>(rowstart + 2 * (NROWS + 1), csr + E0 + E1,
                                     (const __half2*)tH, 128,
                                     (const __half2*)CCH + 128, 256, bl3, (__half2*)h3H);
    // [15] out = h3 @ W3 + b3 (fp32 to d_out)
    {
        GemmJob jo{h3H, W3t, d_out, b3, NROWS, OUTD};
        dim3 g(OUTD / GN, (NROWS + GM - 1) / GM, 1);
        mma_gemm_kernel<false><<<g, 256, GEMM_SMEM>>>(jo, jo, HID);
    }
}

// round 12
// speedup vs baseline: 1.4048x; 1.4048x over previous
#include <cuda_runtime.h>
#include <cuda_fp16.h>
#include <cstdint>

// ---------------------------------------------------------------------------
// Problem constants
// ---------------------------------------------------------------------------
#define NROWS   50000
#define F_IN    768
#define PROJ    1024
#define HID     256
#define OUTD    128
#define NR ((size_t)NROWS)
#define EMAX_TOT 900000

// ---------------------------------------------------------------------------
// Arena of static device scratch (no runtime allocation allowed)
// ---------------------------------------------------------------------------
constexpr size_t OFF_AXH   = 0;                                   // half [NR x 768]
constexpr size_t OFF_CXH   = OFF_AXH + NR * F_IN * 2;             // half [NR x 768]
constexpr size_t OFF_A12H  = OFF_CXH + NR * F_IN * 2;             // half [NR x 512]
constexpr size_t OFF_CCH   = OFF_A12H + NR * 512 * 2;             // half [NR x 512]
constexpr size_t OFF_H1RH  = OFF_CCH + NR * 512 * 2;              // half [NR x 256]
constexpr size_t OFF_TH    = OFF_H1RH + NR * HID * 2;             // half [NR x 256]
constexpr size_t OFF_H1H   = OFF_TH + NR * HID * 2;
constexpr size_t OFF_H2H   = OFF_H1H + NR * HID * 2;
constexpr size_t OFF_H3H   = OFF_H2H + NR * HID * 2;
constexpr size_t OFF_W1H   = OFF_H3H + NR * HID * 2;              // half [768 x 1024]
constexpr size_t OFF_W2H   = OFF_W1H + (size_t)F_IN * PROJ * 2;
constexpr size_t OFF_WL1T  = OFF_W2H + (size_t)F_IN * PROJ * 2;   // half [256 x 1024]
constexpr size_t OFF_WL2T  = OFF_WL1T + (size_t)HID * PROJ * 2;   // contiguous after WL1T!
constexpr size_t OFF_WR1T  = OFF_WL2T + (size_t)HID * PROJ * 2;
constexpr size_t OFF_WAT   = OFF_WR1T + (size_t)HID * PROJ * 2;   // half [512 x 768]
constexpr size_t OFF_WCT   = OFF_WAT + (size_t)512 * F_IN * 2;    // half [512 x 768]
constexpr size_t OFF_WR2T  = OFF_WCT + (size_t)512 * F_IN * 2;    // half [256 x 256]
constexpr size_t OFF_WL3T  = OFF_WR2T + (size_t)HID * HID * 2;
constexpr size_t OFF_W3T   = OFF_WL3T + (size_t)HID * HID * 2;    // half [128 x 256]
constexpr size_t OFF_BA    = OFF_W3T + (size_t)OUTD * HID * 2;    // fp32 [512]
constexpr size_t OFF_BC    = OFF_BA + 512 * 4;                    // fp32 [512]
constexpr size_t OFF_CNT   = OFF_BC + 512 * 4;                    // int [3 x 50000]
constexpr size_t OFF_ROWST = OFF_CNT + 3 * NR * 4;                // int [3 x 50001]
constexpr size_t OFF_CURSOR= OFF_ROWST + 3 * (NR + 1) * 4;        // int [3 x 50000]
constexpr size_t OFF_CSR   = OFF_CURSOR + 3 * NR * 4;             // int [900000]
constexpr size_t ARENA_TOTAL = OFF_CSR + (size_t)EMAX_TOT * 4 + 64;

__device__ unsigned char g_arena[ARENA_TOTAL];

__device__ __forceinline__ uint32_t smem_u32(const void* p) {
    uint32_t a;
    asm("{ .reg .u64 t; cvta.to.shared.u64 t, %1; cvt.u32.u64 %0, t; }" : "=r"(a) : "l"(p));
    return a;
}

// ---------------------------------------------------------------------------
// Batched tensor-core GEMM via mma.sync:
//   C[M,N] = A[M,K](fp16) @ B[N,K](fp16)^T (+bias), fp32 accumulate.
// Tile 128x128x32, 8 warps (4Mx2N), 3-stage cp.async pipeline (2-deep
// prefetch — measured optimum; 3-deep oversubscribes the L1tex queue).
// GRID ORDER: blockIdx.x = N-block (fastest) so CTAs sharing an A row-tile
// are bid-adjacent -> same wave -> A tile read once from DRAM, rest L2 hits.
// blockIdx.z selects one of two independent jobs (batched launch).
// smem rows padded to 40 halfs (80B stride -> conflict-free ldmatrix).
// Requires: N % 128 == 0, K % 32 == 0. M arbitrary.
// ---------------------------------------------------------------------------
#define GM 128
#define GN 128
#define GK 32
#define SROW 40
#define STAGES 3
#define ABYTES (GM * SROW * 2)            // 10240
#define STAGE_BYTES (2 * ABYTES)          // A + B per stage
#define GEMM_SMEM (STAGES * STAGE_BYTES)  // 61440

struct GemmJob {
    const __half* A;
    const __half* B;
    void* C;
    const float* bias;
    int M;
    int ldc;
};

template<bool HALF_OUT>
__global__ void __launch_bounds__(256, 2)
mma_gemm_kernel(GemmJob j0, GemmJob j1, int K)
{
    const GemmJob j = (blockIdx.z == 0) ? j0 : j1;
    const int m0 = blockIdx.y * GM;           // M on y (slow axis)
    if (m0 >= j.M) return;
    const int n0 = blockIdx.x * GN;           // N on x (fast axis -> L2 reuse of A)

    extern __shared__ __align__(16) char dynsmem[];
    const uint32_t sbase = smem_u32(dynsmem);

    const int tid = threadIdx.x;
    const int lane = tid & 31, wid = tid >> 5;
    const int warp_m = wid >> 1, warp_n = wid & 1;
    const int nk = K / GK;

    float acc[2][8][4];
#pragma unroll
    for (int i = 0; i < 2; i++)
#pragma unroll
        for (int jj = 0; jj < 8; jj++)
#pragma unroll
            for (int q = 0; q < 4; q++) acc[i][jj][q] = 0.f;

    auto issue = [&](int ch) {
        int st = ch % STAGES;
        int k0 = ch * GK;
        uint32_t baseA = sbase + st * STAGE_BYTES;
        uint32_t baseB = baseA + ABYTES;
#pragma unroll
        for (int i = 0; i < 2; i++) {
            int idx = tid + i * 256;          // 0..511
            int row = idx >> 2;               // 0..127
            int c8  = (idx & 3) << 3;         // 0,8,16,24
            uint32_t soff = (uint32_t)(row * SROW + c8) * 2;
            int gr = m0 + row;
            const __half* ga = j.A + (size_t)(gr < j.M ? gr : 0) * K + k0 + c8;
            int sz = (gr < j.M) ? 16 : 0;
            asm volatile("cp.async.cg.shared.global [%0], [%1], 16, %2;"
                         :: "r"(baseA + soff), "l"(ga), "r"(sz));
            const __half* gb = j.B + (size_t)(n0 + row) * K + k0 + c8;
            asm volatile("cp.async.cg.shared.global [%0], [%1], 16;"
                         :: "r"(baseB + soff), "l"(gb));
        }
        asm volatile("cp.async.commit_group;");
    };

    issue(0);
    if (nk > 1) issue(1);

    for (int ch = 0; ch < nk; ch++) {
        if (ch + 1 < nk) asm volatile("cp.async.wait_group 1;");
        else             asm volatile("cp.async.wait_group 0;");
        __syncthreads();
        if (ch + 2 < nk) issue(ch + 2);

        int st = ch % STAGES;
        uint32_t baseA = sbase + st * STAGE_BYTES;
        uint32_t baseB = baseA + ABYTES;
#pragma unroll
        for (int ks = 0; ks < 2; ks++) {
            int kk = ks * 16;
            uint32_t a[2][4];
#pragma unroll
            for (int wm = 0; wm < 2; wm++) {
                int row = warp_m * 32 + wm * 16 + (lane & 15);
                int col = kk + ((lane >> 4) << 3);
                uint32_t addr = baseA + (uint32_t)(row * SROW + col) * 2;
                asm volatile("ldmatrix.sync.aligned.m8n8.x4.shared.b16 {%0,%1,%2,%3}, [%4];"
                             : "=r"(a[wm][0]), "=r"(a[wm][1]), "=r"(a[wm][2]), "=r"(a[wm][3])
                             : "r"(addr));
            }
            uint32_t b[8][2];
#pragma unroll
            for (int p = 0; p < 4; p++) {
                int n = warp_n * 64 + p * 16 + (lane & 7) + ((lane >> 4) << 3);
                int col = kk + (((lane >> 3) & 1) << 3);
                uint32_t addr = baseB + (uint32_t)(n * SROW + col) * 2;
                uint32_t r0, r1, r2, r3;
                asm volatile("ldmatrix.sync.aligned.m8n8.x4.shared.b16 {%0,%1,%2,%3}, [%4];"
                             : "=r"(r0), "=r"(r1), "=r"(r2), "=r"(r3) : "r"(addr));
                b[2 * p][0] = r0; b[2 * p][1] = r1;
                b[2 * p + 1][0] = r2; b[2 * p + 1][1] = r3;
            }
#pragma unroll
            for (int wm = 0; wm < 2; wm++)
#pragma unroll
                for (int wn = 0; wn < 8; wn++)
                    asm volatile(
                        "mma.sync.aligned.m16n8k16.row.col.f32.f16.f16.f32 "
                        "{%0,%1,%2,%3}, {%4,%5,%6,%7}, {%8,%9}, {%0,%1,%2,%3};"
                        : "+f"(acc[wm][wn][0]), "+f"(acc[wm][wn][1]),
                          "+f"(acc[wm][wn][2]), "+f"(acc[wm][wn][3])
                        : "r"(a[wm][0]), "r"(a[wm][1]), "r"(a[wm][2]), "r"(a[wm][3]),
                          "r"(b[wn][0]), "r"(b[wn][1]));
        }
        __syncthreads();
    }

    // Epilogue
    float* Cf = (float*)j.C;
    __half* Ch = (__half*)j.C;
#pragma unroll
    for (int wm = 0; wm < 2; wm++) {
        int r = m0 + warp_m * 32 + wm * 16 + (lane >> 2);
#pragma unroll
        for (int wn = 0; wn < 8; wn++) {
            int c = n0 + warp_n * 64 + wn * 8 + ((lane & 3) << 1);
            float b0 = 0.f, b1 = 0.f;
            if (j.bias) { b0 = j.bias[c]; b1 = j.bias[c + 1]; }
            if (r < j.M) {
                float v0 = acc[wm][wn][0] + b0, v1 = acc[wm][wn][1] + b1;
                if (HALF_OUT)
                    *(__half2*)(Ch + (size_t)r * j.ldc + c) = __floats2half2_rn(v0, v1);
                else
                    *(float2*)(Cf + (size_t)r * j.ldc + c) = make_float2(v0, v1);
            }
            if (r + 8 < j.M) {
                float v0 = acc[wm][wn][2] + b0, v1 = acc[wm][wn][3] + b1;
                if (HALF_OUT)
                    *(__half2*)(Ch + (size_t)(r + 8) * j.ldc + c) = __floats2half2_rn(v0, v1);
                else
                    *(float2*)(Cf + (size_t)(r + 8) * j.ldc + c) = make_float2(v0, v1);
            }
        }
    }
}

// ---------------------------------------------------------------------------
// Dual fp32->fp16 conversion (two tensors, one launch)
// ---------------------------------------------------------------------------
__global__ void tohalf2_kernel(const float4* __restrict__ x0, __half2* __restrict__ o0,
                               const float4* __restrict__ x1, __half2* __restrict__ o1,
                               int n4)
{
    int i = blockIdx.x * blockDim.x + threadIdx.x;
    const float4* x; __half2* o; int j;
    if (i < n4)          { x = x0; o = o0; j = i; }
    else if (i < 2 * n4) { x = x1; o = o1; j = i - n4; }
    else return;
    float4 v = x[j];
    o[2 * j]     = __floats2half2_rn(v.x, v.y);
    o[2 * j + 1] = __floats2half2_rn(v.z, v.w);
}

// ---------------------------------------------------------------------------
// Batched prep: 7 transposes (fp32 [KxN] -> fp16 [NxK]) + 3 bias folds + zero
// ---------------------------------------------------------------------------
__device__ __forceinline__ void tjob(const float* __restrict__ W, __half* __restrict__ T,
                                     int K, int N, int local)
{
    int k = local / N, n = local % N;
    T[(size_t)n * K + k] = __float2half(W[local]);
}
__device__ __forceinline__ void vjob(const float* __restrict__ b, const float* __restrict__ W,
                                     float* __restrict__ out, int K, int c)
{
    float a0 = 0.f, a1 = 0.f, a2 = 0.f, a3 = 0.f;
    for (int k = 0; k < K; k += 4) {
        a0 += b[k]     * W[(size_t)k * 256 + c];
        a1 += b[k + 1] * W[(size_t)(k + 1) * 256 + c];
        a2 += b[k + 2] * W[(size_t)(k + 2) * 256 + c];
        a3 += b[k + 3] * W[(size_t)(k + 3) * 256 + c];
    }
    out[c] = (a0 + a1) + (a2 + a3);
}

#define TBLOCKS 4480   // 1146880 / 256

__global__ void prep_kernel(
    const float* Wl1, const float* Wl2, const float* Wr1,
    const float* Wr2, const float* Wl3, const float* W3, const float* Wr3,
    __half* Wl1t, __half* Wl2t, __half* Wr1t,
    __half* Wr2t, __half* Wl3t, __half* W3t, __half* Wr3t,
    const float* b1, const float* b2, float* bA, float* bC)
{
    int blk = blockIdx.x;
    if (blk < TBLOCKS) {
        int t = blk * 256 + threadIdx.x;
        if      (t <  262144) tjob(Wl1, Wl1t, 1024, 256, t);
        else if (t <  524288) tjob(Wl2, Wl2t, 1024, 256, t - 262144);
        else if (t <  786432) tjob(Wr1, Wr1t, 1024, 256, t - 524288);
        else if (t <  851968) tjob(Wr2, Wr2t,  256, 256, t - 786432);
        else if (t <  917504) tjob(Wl3, Wl3t,  256, 256, t - 851968);
        else if (t <  950272) tjob(W3,  W3t,   256, 128, t - 917504);
        else                  tjob(Wr3, Wr3t,  768, 256, t - 950272);
    } else {
        int which = blk - TBLOCKS;
        int c = threadIdx.x;
        if (which == 0) vjob(b1, Wl1, bA, 1024, c);
        else if (which == 1) vjob(b1, Wl2, bA + 256, 1024, c);
        else { vjob(b2, Wr1, bC, 1024, c); bC[256 + c] = 0.f; }
    }
}

// ---------------------------------------------------------------------------
// CSR build for all 3 graphs, batched
// ---------------------------------------------------------------------------
__global__ void count3_kernel(const int* __restrict__ e0, int E0,
                              const int* __restrict__ e1, int E1,
                              const int* __restrict__ e2, int E2,
                              int* __restrict__ cnt)
{
    int t = blockIdx.x * blockDim.x + threadIdx.x;
    if (t < E0)                atomicAdd(&cnt[e0[E0 + t]], 1);
    else if (t < E0 + E1)      atomicAdd(&cnt[NROWS + e1[E1 + (t - E0)]], 1);
    else if (t < E0 + E1 + E2) atomicAdd(&cnt[2 * NROWS + e2[E2 + (t - E0 - E1)]], 1);
}

__global__ void scan3_kernel(const int* __restrict__ cnt,
                             int* __restrict__ rowstart, int* __restrict__ cursor)
{
    __shared__ int warp_sums[32];
    __shared__ int s_carry;
    int g = blockIdx.x;
    const int* c = cnt + (size_t)g * NROWS;
    int* rs = rowstart + (size_t)g * (NROWS + 1);
    int* cu = cursor + (size_t)g * NROWS;
    int tid = threadIdx.x, lane = tid & 31, wid = tid >> 5;
    if (tid == 0) s_carry = 0;
    __syncthreads();
    for (int base = 0; base < NROWS; base += 1024) {
        int i = base + tid;
        int v = (i < NROWS) ? c[i] : 0;
        int x = v;
#pragma unroll
        for (int off = 1; off < 32; off <<= 1) {
            int y = __shfl_up_sync(0xffffffffu, x, off);
            if (lane >= off) x += y;
        }
        if (lane == 31) warp_sums[wid] = x;
        __syncthreads();
        if (wid == 0) {
            int w = warp_sums[lane];
#pragma unroll
            for (int off = 1; off < 32; off <<= 1) {
                int y = __shfl_up_sync(0xffffffffu, w, off);
                if (lane >= off) w += y;
            }
            warp_sums[lane] = w;
        }
        __syncthreads();
        int warp_off = (wid > 0) ? warp_sums[wid - 1] : 0;
        int incl = x + warp_off;
        int carry = s_carry;
        if (i < NROWS) { int ex = carry + incl - v; rs[i] = ex; cu[i] = ex; }
        __syncthreads();
        if (tid == 1023) s_carry = carry + incl;
        __syncthreads();
    }
    if (tid == 0) rs[NROWS] = s_carry;
}

__global__ void fill3_kernel(const int* __restrict__ e0, int E0,
                             const int* __restrict__ e1, int E1,
                             const int* __restrict__ e2, int E2,
                             int* __restrict__ cursor, int* __restrict__ csr)
{
    int t = blockIdx.x * blockDim.x + threadIdx.x;
    if (t < E0) {
        int p = atomicAdd(&cursor[e0[E0 + t]], 1);
        csr[p] = e0[t];
    } else if (t < E0 + E1) {
        int j = t - E0;
        int p = atomicAdd(&cursor[NROWS + e1[E1 + j]], 1);
        csr[E0 + p] = e1[j];
    } else if (t < E0 + E1 + E2) {
        int j = t - E0 - E1;
        int p = atomicAdd(&cursor[2 * NROWS + e2[E2 + j]], 1);
        csr[E0 + E1 + p] = e2[j];
    }
}

// ---------------------------------------------------------------------------
// Fused mean-aggregate + bias + residual + ReLU (half2 wide, unroll-4 MLP)
// 2 rows per 256-thread block (halves CTA count vs 1 row/128 threads).
// out(r,:) = relu( mean_{s in row r} S[s,:] + bias + other[r,:] ), fp16 in/out
// ---------------------------------------------------------------------------
__global__ void __launch_bounds__(256)
aggregate_kernel(const int* __restrict__ rowstart, const int* __restrict__ csr,
                 const __half2* __restrict__ S2, int ldS2,
                 const __half2* __restrict__ other2, int ldO2,
                 const float* __restrict__ bias,
                 __half2* __restrict__ out2)
{
    int r = blockIdx.x * 2 + (threadIdx.x >> 7);
    int c2 = threadIdx.x & 127;
    int s = rowstart[r], e = rowstart[r + 1];
    float ax = 0.f, ay = 0.f, bx = 0.f, by = 0.f;
    int i = s;
    for (; i + 4 <= e; i += 4) {
        int i0 = csr[i], i1 = csr[i + 1], i2 = csr[i + 2], i3 = csr[i + 3];
        float2 v0 = __half22float2(S2[(size_t)i0 * ldS2 + c2]);
        float2 v1 = __half22float2(S2[(size_t)i1 * ldS2 + c2]);
        float2 v2 = __half22float2(S2[(size_t)i2 * ldS2 + c2]);
        float2 v3 = __half22float2(S2[(size_t)i3 * ldS2 + c2]);
        ax += v0.x + v1.x; ay += v0.y + v1.y;
        bx += v2.x + v3.x; by += v2.y + v3.y;
    }
    for (; i < e; i++) {
        float2 v = __half22float2(S2[(size_t)csr[i] * ldS2 + c2]);
        ax += v.x; ay += v.y;
    }
    float inv = 1.f / fmaxf((float)(e - s), 1.f);
    float2 oth = __half22float2(other2[(size_t)r * ldO2 + c2]);
    float bb0 = bias[2 * c2], bb1 = bias[2 * c2 + 1];
    float vx = fmaxf((ax + bx) * inv + bb0 + oth.x, 0.f);
    float vy = fmaxf((ay + by) * inv + bb1 + oth.y, 0.f);
    out2[(size_t)r * 128 + c2] = __floats2half2_rn(vx, vy);
}

// ---------------------------------------------------------------------------
// Host helpers  (grid: x = N-blocks [fast], y = M-blocks, z = job)
// ---------------------------------------------------------------------------
static inline void gemm1_f16(int M, int N, int K, const __half* A, const __half* B,
                             __half* C, int ldc, const float* bias)
{
    GemmJob j{A, B, (void*)C, bias, M, ldc};
    dim3 g(N / GN, (M + GM - 1) / GM, 1);
    mma_gemm_kernel<true><<<g, 256, GEMM_SMEM>>>(j, j, K);
}

extern "C" void kernel_launch(void* const* d_in, const int* in_sizes, int n_in,
                              void* d_out, int out_size)
{
    const float* article_x   = (const float*)d_in[0];
    const float* community_x = (const float*)d_in[1];
    const int*   e_wb        = (const int*)d_in[2];
    const int*   e_mb        = (const int*)d_in[3];
    const int*   e_int       = (const int*)d_in[4];
    const float* W1  = (const float*)d_in[5];
    const float* b1  = (const float*)d_in[6];
    const float* W2  = (const float*)d_in[7];
    const float* b2  = (const float*)d_in[8];
    const float* Wl1 = (const float*)d_in[9];
    const float* bl1 = (const float*)d_in[10];
    const float* Wr1 = (const float*)d_in[11];
    const float* Wl2 = (const float*)d_in[12];
    const float* bl2 = (const float*)d_in[13];
    const float* Wr2 = (const float*)d_in[14];
    const float* Wl3 = (const float*)d_in[15];
    const float* bl3 = (const float*)d_in[16];
    const float* Wr3 = (const float*)d_in[17];
    const float* W3  = (const float*)d_in[18];
    const float* b3  = (const float*)d_in[19];

    const int E0 = in_sizes[2] / 2;   // e_wb
    const int E1 = in_sizes[3] / 2;   // e_mb
    const int E2 = in_sizes[4] / 2;   // e_int

    cudaFuncSetAttribute(mma_gemm_kernel<true>,
                         cudaFuncAttributeMaxDynamicSharedMemorySize, GEMM_SMEM);
    cudaFuncSetAttribute(mma_gemm_kernel<false>,
                         cudaFuncAttributeMaxDynamicSharedMemorySize, GEMM_SMEM);

    unsigned char* arena;
    cudaGetSymbolAddress((void**)&arena, g_arena);
#define AP(T, off) ((T*)(arena + (off)))
    __half *AxH  = AP(__half, OFF_AXH),  *CxH  = AP(__half, OFF_CXH);
    __half *A12H = AP(__half, OFF_A12H), *CCH  = AP(__half, OFF_CCH);
    __half *h1rH = AP(__half, OFF_H1RH), *tH   = AP(__half, OFF_TH);
    __half *h1H  = AP(__half, OFF_H1H), *h2H = AP(__half, OFF_H2H), *h3H = AP(__half, OFF_H3H);
    __half *W1H  = AP(__half, OFF_W1H), *W2H = AP(__half, OFF_W2H);
    __half *Wl1t = AP(__half, OFF_WL1T), *Wl2t = AP(__half, OFF_WL2T), *Wr1t = AP(__half, OFF_WR1T);
    __half *WAt  = AP(__half, OFF_WAT),  *WCt  = AP(__half, OFF_WCT);
    __half *Wr2t = AP(__half, OFF_WR2T), *Wl3t = AP(__half, OFF_WL3T), *W3t = AP(__half, OFF_W3T);
    float  *bA   = AP(float, OFF_BA),    *bC   = AP(float, OFF_BC);
    int *cnt = AP(int, OFF_CNT), *rowstart = AP(int, OFF_ROWST);
    int *cursor = AP(int, OFF_CURSOR), *csr = AP(int, OFF_CSR);

    // [1] W1,W2 -> fp16
    {
        int n4 = F_IN * PROJ / 4;
        tohalf2_kernel<<<(2 * n4 + 255) / 256, 256>>>(
            (const float4*)W1, (__half2*)W1H, (const float4*)W2, (__half2*)W2H, n4);
    }
    // [2] all transposes + bias folds + bC zero
    prep_kernel<<<TBLOCKS + 3, 256>>>(Wl1, Wl2, Wr1, Wr2, Wl3, W3, Wr3,
                                      Wl1t, Wl2t, Wr1t, Wr2t, Wl3t, W3t,
                                      WCt + (size_t)256 * F_IN,
                                      b1, b2, bA, bC);
    // [3] BOTH weight folds in one batched launch (z=2)
    //   z0: WAt[512,768] = [Wl1t;Wl2t] @ W1H^T    z1: WCt[0:256] = Wr1t @ W2H^T
    {
        GemmJob ja{Wl1t, W1H, (void*)WAt, nullptr, 512, F_IN};
        GemmJob jc{Wr1t, W2H, (void*)WCt, nullptr, HID, F_IN};
        dim3 g(F_IN / GN, 512 / GM, 2);
        mma_gemm_kernel<true><<<g, 256, GEMM_SMEM>>>(ja, jc, PROJ);
    }
    // [4] activations -> fp16
    {
        int n4 = (int)(NR * F_IN / 4);
        tohalf2_kernel<<<(2 * n4 + 255) / 256, 256>>>(
            (const float4*)article_x, (__half2*)AxH,
            (const float4*)community_x, (__half2*)CxH, n4);
    }
    // [5] BOTH big projections in one batched launch (z=2), fp16 outputs
    //   z0: A12H = article_x @ [W1Wl1|W1Wl2] + bA    z1: CCH = community_x @ [W2Wr1|Wr3] + bC
    {
        GemmJob ja{AxH, WAt, (void*)A12H, bA, NROWS, 512};
        GemmJob jc{CxH, WCt, (void*)CCH, bC, NROWS, 512};
        dim3 g(512 / GN, (NROWS + GM - 1) / GM, 2);
        mma_gemm_kernel<true><<<g, 256, GEMM_SMEM>>>(ja, jc, F_IN);
    }

    // [6-9] CSR build for all three graphs
    cudaMemsetAsync(cnt, 0, 3 * NROWS * sizeof(int));
    {
        int Etot = E0 + E1 + E2;
        count3_kernel<<<(Etot + 255) / 256, 256>>>(e_wb, E0, e_mb, E1, e_int, E2, cnt);
        scan3_kernel<<<3, 1024>>>(cnt, rowstart, cursor);
        fill3_kernel<<<(Etot + 255) / 256, 256>>>(e_wb, E0, e_mb, E1, e_int, E2, cursor, csr);
    }

    // [10] conv1: h1 = relu(mean(A1[src]) + bl1 + C1)
    aggregate_kernel<<<NROWS / 2, 256>>>(rowstart, csr,
                                         (const __half2*)A12H, 256,
                                         (const __half2*)CCH, 256, bl1, (__half2*)h1H);
    // [11] h1r = h1 @ Wr2  (fp16)
    gemm1_f16(NROWS, HID, HID, h1H, Wr2t, h1rH, HID, nullptr);
    // [12] conv2: h2 = relu(mean(A2[src]) + bl2 + h1r)
    aggregate_kernel<<<NROWS / 2, 256>>>(rowstart + (NROWS + 1), csr + E0,
                                         (const __half2*)(A12H + HID), 256,
                                         (const __half2*)h1rH, 128, bl2, (__half2*)h2H);
    // [13] t = h2 @ Wl3 (fp16: gather source)
    gemm1_f16(NROWS, HID, HID, h2H, Wl3t, tH, HID, nullptr);
    // [14] conv3: h3 = relu(mean(t[src]) + bl3 + CC[:,256:512])
    aggregate_kernel<<<NROWS / 2, 256>>>(rowstart + 2 * (NROWS + 1), csr + E0 + E1,
                                         (const __half2*)tH, 128,
                                         (const __half2*)CCH + 128, 256, bl3, (__half2*)h3H);
    // [15] out = h3 @ W3 + b3 (fp32 to d_out)
    {
        GemmJob jo{h3H, W3t, d_out, b3, NROWS, OUTD};
        dim3 g(OUTD / GN, (NROWS + GM - 1) / GM, 1);
        mma_gemm_kernel<false><<<g, 256, GEMM_SMEM>>>(jo, jo, HID);
    }
}

// round 13
// speedup vs baseline: 1.4176x; 1.0091x over previous
#include <cuda_runtime.h>
#include <cuda_fp16.h>
#include <cstdint>

// ---------------------------------------------------------------------------
// Problem constants
// ---------------------------------------------------------------------------
#define NROWS   50000
#define F_IN    768
#define PROJ    1024
#define HID     256
#define OUTD    128
#define NR ((size_t)NROWS)
#define EMAX_TOT 900000

// ---------------------------------------------------------------------------
// Arena of static device scratch (no runtime allocation allowed)
// ---------------------------------------------------------------------------
constexpr size_t OFF_AXH   = 0;                                   // half [NR x 768]
constexpr size_t OFF_CXH   = OFF_AXH + NR * F_IN * 2;             // half [NR x 768]
constexpr size_t OFF_A12H  = OFF_CXH + NR * F_IN * 2;             // half [NR x 512]
constexpr size_t OFF_CCH   = OFF_A12H + NR * 512 * 2;             // half [NR x 512]
constexpr size_t OFF_H1RH  = OFF_CCH + NR * 512 * 2;              // half [NR x 256]
constexpr size_t OFF_TH    = OFF_H1RH + NR * HID * 2;             // half [NR x 256]
constexpr size_t OFF_H1H   = OFF_TH + NR * HID * 2;
constexpr size_t OFF_H2H   = OFF_H1H + NR * HID * 2;
constexpr size_t OFF_H3H   = OFF_H2H + NR * HID * 2;
constexpr size_t OFF_W1H   = OFF_H3H + NR * HID * 2;              // half [768 x 1024]
constexpr size_t OFF_W2H   = OFF_W1H + (size_t)F_IN * PROJ * 2;
constexpr size_t OFF_WL1T  = OFF_W2H + (size_t)F_IN * PROJ * 2;   // half [256 x 1024]
constexpr size_t OFF_WL2T  = OFF_WL1T + (size_t)HID * PROJ * 2;   // contiguous after WL1T!
constexpr size_t OFF_WR1T  = OFF_WL2T + (size_t)HID * PROJ * 2;
constexpr size_t OFF_WAT   = OFF_WR1T + (size_t)HID * PROJ * 2;   // half [512 x 768]
constexpr size_t OFF_WCT   = OFF_WAT + (size_t)512 * F_IN * 2;    // half [512 x 768]
constexpr size_t OFF_WR2T  = OFF_WCT + (size_t)512 * F_IN * 2;    // half [256 x 256]
constexpr size_t OFF_WL3T  = OFF_WR2T + (size_t)HID * HID * 2;
constexpr size_t OFF_W3T   = OFF_WL3T + (size_t)HID * HID * 2;    // half [128 x 256]
constexpr size_t OFF_BA    = OFF_W3T + (size_t)OUTD * HID * 2;    // fp32 [512]
constexpr size_t OFF_BC    = OFF_BA + 512 * 4;                    // fp32 [512]
constexpr size_t OFF_CNT   = OFF_BC + 512 * 4;                    // int [3 x 50000]
constexpr size_t OFF_ROWST = OFF_CNT + 3 * NR * 4;                // int [3 x 50001]
constexpr size_t OFF_CURSOR= OFF_ROWST + 3 * (NR + 1) * 4;        // int [3 x 50000]
constexpr size_t OFF_CSR   = OFF_CURSOR + 3 * NR * 4;             // int [900000]
constexpr size_t ARENA_TOTAL = OFF_CSR + (size_t)EMAX_TOT * 4 + 64;

__device__ unsigned char g_arena[ARENA_TOTAL];

__device__ __forceinline__ uint32_t smem_u32(const void* p) {
    uint32_t a;
    asm("{ .reg .u64 t; cvta.to.shared.u64 t, %1; cvt.u32.u64 %0, t; }" : "=r"(a) : "l"(p));
    return a;
}

// ---------------------------------------------------------------------------
// Common GEMM config
// ---------------------------------------------------------------------------
#define GM 128
#define GN 128
#define GK 32
#define SROW 40
#define STAGES 3
#define ABYTES (GM * SROW * 2)            // 10240
#define STAGE_BYTES (2 * ABYTES)          // A + B per stage
#define GEMM_SMEM (STAGES * STAGE_BYTES)  // 61440

struct GemmJob {
    const __half* A;
    const __half* B;
    void* C;
    const float* bias;
    int M;
    int ldc;
};

// ---------------------------------------------------------------------------
// 8-warp GEMM (warp tile 32x64) — proven baseline, used for folds/small GEMMs.
//   C[M,N] = A[M,K](fp16) @ B[N,K](fp16)^T (+bias), fp32 accumulate.
// ---------------------------------------------------------------------------
template<bool HALF_OUT>
__global__ void __launch_bounds__(256, 2)
mma_gemm_kernel(GemmJob j0, GemmJob j1, int K)
{
    const GemmJob j = (blockIdx.z == 0) ? j0 : j1;
    const int m0 = blockIdx.y * GM;
    if (m0 >= j.M) return;
    const int n0 = blockIdx.x * GN;

    extern __shared__ __align__(16) char dynsmem[];
    const uint32_t sbase = smem_u32(dynsmem);

    const int tid = threadIdx.x;
    const int lane = tid & 31, wid = tid >> 5;
    const int warp_m = wid >> 1, warp_n = wid & 1;
    const int nk = K / GK;

    float acc[2][8][4];
#pragma unroll
    for (int i = 0; i < 2; i++)
#pragma unroll
        for (int jj = 0; jj < 8; jj++)
#pragma unroll
            for (int q = 0; q < 4; q++) acc[i][jj][q] = 0.f;

    auto issue = [&](int ch) {
        int st = ch % STAGES;
        int k0 = ch * GK;
        uint32_t baseA = sbase + st * STAGE_BYTES;
        uint32_t baseB = baseA + ABYTES;
#pragma unroll
        for (int i = 0; i < 2; i++) {
            int idx = tid + i * 256;
            int row = idx >> 2;
            int c8  = (idx & 3) << 3;
            uint32_t soff = (uint32_t)(row * SROW + c8) * 2;
            int gr = m0 + row;
            const __half* ga = j.A + (size_t)(gr < j.M ? gr : 0) * K + k0 + c8;
            int sz = (gr < j.M) ? 16 : 0;
            asm volatile("cp.async.cg.shared.global [%0], [%1], 16, %2;"
                         :: "r"(baseA + soff), "l"(ga), "r"(sz));
            const __half* gb = j.B + (size_t)(n0 + row) * K + k0 + c8;
            asm volatile("cp.async.cg.shared.global [%0], [%1], 16;"
                         :: "r"(baseB + soff), "l"(gb));
        }
        asm volatile("cp.async.commit_group;");
    };

    issue(0);
    if (nk > 1) issue(1);

    for (int ch = 0; ch < nk; ch++) {
        if (ch + 1 < nk) asm volatile("cp.async.wait_group 1;");
        else             asm volatile("cp.async.wait_group 0;");
        __syncthreads();
        if (ch + 2 < nk) issue(ch + 2);

        int st = ch % STAGES;
        uint32_t baseA = sbase + st * STAGE_BYTES;
        uint32_t baseB = baseA + ABYTES;
#pragma unroll
        for (int ks = 0; ks < 2; ks++) {
            int kk = ks * 16;
            uint32_t a[2][4];
#pragma unroll
            for (int wm = 0; wm < 2; wm++) {
                int row = warp_m * 32 + wm * 16 + (lane & 15);
                int col = kk + ((lane >> 4) << 3);
                uint32_t addr = baseA + (uint32_t)(row * SROW + col) * 2;
                asm volatile("ldmatrix.sync.aligned.m8n8.x4.shared.b16 {%0,%1,%2,%3}, [%4];"
                             : "=r"(a[wm][0]), "=r"(a[wm][1]), "=r"(a[wm][2]), "=r"(a[wm][3])
                             : "r"(addr));
            }
            uint32_t b[8][2];
#pragma unroll
            for (int p = 0; p < 4; p++) {
                int n = warp_n * 64 + p * 16 + (lane & 7) + ((lane >> 4) << 3);
                int col = kk + (((lane >> 3) & 1) << 3);
                uint32_t addr = baseB + (uint32_t)(n * SROW + col) * 2;
                uint32_t r0, r1, r2, r3;
                asm volatile("ldmatrix.sync.aligned.m8n8.x4.shared.b16 {%0,%1,%2,%3}, [%4];"
                             : "=r"(r0), "=r"(r1), "=r"(r2), "=r"(r3) : "r"(addr));
                b[2 * p][0] = r0; b[2 * p][1] = r1;
                b[2 * p + 1][0] = r2; b[2 * p + 1][1] = r3;
            }
#pragma unroll
            for (int wm = 0; wm < 2; wm++)
#pragma unroll
                for (int wn = 0; wn < 8; wn++)
                    asm volatile(
                        "mma.sync.aligned.m16n8k16.row.col.f32.f16.f16.f32 "
                        "{%0,%1,%2,%3}, {%4,%5,%6,%7}, {%8,%9}, {%0,%1,%2,%3};"
                        : "+f"(acc[wm][wn][0]), "+f"(acc[wm][wn][1]),
                          "+f"(acc[wm][wn][2]), "+f"(acc[wm][wn][3])
                        : "r"(a[wm][0]), "r"(a[wm][1]), "r"(a[wm][2]), "r"(a[wm][3]),
                          "r"(b[wn][0]), "r"(b[wn][1]));
        }
        __syncthreads();
    }

    float* Cf = (float*)j.C;
    __half* Ch = (__half*)j.C;
#pragma unroll
    for (int wm = 0; wm < 2; wm++) {
        int r = m0 + warp_m * 32 + wm * 16 + (lane >> 2);
#pragma unroll
        for (int wn = 0; wn < 8; wn++) {
            int c = n0 + warp_n * 64 + wn * 8 + ((lane & 3) << 1);
            float b0 = 0.f, b1 = 0.f;
            if (j.bias) { b0 = j.bias[c]; b1 = j.bias[c + 1]; }
            if (r < j.M) {
                float v0 = acc[wm][wn][0] + b0, v1 = acc[wm][wn][1] + b1;
                if (HALF_OUT)
                    *(__half2*)(Ch + (size_t)r * j.ldc + c) = __floats2half2_rn(v0, v1);
                else
                    *(float2*)(Cf + (size_t)r * j.ldc + c) = make_float2(v0, v1);
            }
            if (r + 8 < j.M) {
                float v0 = acc[wm][wn][2] + b0, v1 = acc[wm][wn][3] + b1;
                if (HALF_OUT)
                    *(__half2*)(Ch + (size_t)(r + 8) * j.ldc + c) = __floats2half2_rn(v0, v1);
                else
                    *(float2*)(Cf + (size_t)(r + 8) * j.ldc + c) = make_float2(v0, v1);
            }
        }
    }
}

// ---------------------------------------------------------------------------
// 4-warp BIG-TILE GEMM (warp tile 64x64, 2Mx2N warps, 128 acc regs/thread).
// Same 128x128x32 CTA tile and smem layout, but ldmatrix traffic per k-step
// drops from 24KB -> 16KB (each fragment feeds 8 MMAs). Used ONLY for the
// L1-bound big projection launch.
// ---------------------------------------------------------------------------
__global__ void __launch_bounds__(128, 2)
mma_gemm_big_kernel(GemmJob j0, GemmJob j1, int K)
{
    const GemmJob j = (blockIdx.z == 0) ? j0 : j1;
    const int m0 = blockIdx.y * GM;
    if (m0 >= j.M) return;
    const int n0 = blockIdx.x * GN;

    extern __shared__ __align__(16) char dynsmem[];
    const uint32_t sbase = smem_u32(dynsmem);

    const int tid = threadIdx.x;              // 0..127
    const int lane = tid & 31, wid = tid >> 5; // 4 warps
    const int warp_m = wid >> 1, warp_n = wid & 1;
    const int nk = K / GK;

    float acc[4][8][4];
#pragma unroll
    for (int i = 0; i < 4; i++)
#pragma unroll
        for (int jj = 0; jj < 8; jj++)
#pragma unroll
            for (int q = 0; q < 4; q++) acc[i][jj][q] = 0.f;

    auto issue = [&](int ch) {
        int st = ch % STAGES;
        int k0 = ch * GK;
        uint32_t baseA = sbase + st * STAGE_BYTES;
        uint32_t baseB = baseA + ABYTES;
#pragma unroll
        for (int i = 0; i < 4; i++) {
            int idx = tid + i * 128;          // 0..511
            int row = idx >> 2;               // 0..127
            int c8  = (idx & 3) << 3;
            uint32_t soff = (uint32_t)(row * SROW + c8) * 2;
            int gr = m0 + row;
            const __half* ga = j.A + (size_t)(gr < j.M ? gr : 0) * K + k0 + c8;
            int sz = (gr < j.M) ? 16 : 0;
            asm volatile("cp.async.cg.shared.global [%0], [%1], 16, %2;"
                         :: "r"(baseA + soff), "l"(ga), "r"(sz));
            const __half* gb = j.B + (size_t)(n0 + row) * K + k0 + c8;
            asm volatile("cp.async.cg.shared.global [%0], [%1], 16;"
                         :: "r"(baseB + soff), "l"(gb));
        }
        asm volatile("cp.async.commit_group;");
    };

    issue(0);
    if (nk > 1) issue(1);

    for (int ch = 0; ch < nk; ch++) {
        if (ch + 1 < nk) asm volatile("cp.async.wait_group 1;");
        else             asm volatile("cp.async.wait_group 0;");
        __syncthreads();
        if (ch + 2 < nk) issue(ch + 2);

        int st = ch % STAGES;
        uint32_t baseA = sbase + st * STAGE_BYTES;
        uint32_t baseB = baseA + ABYTES;
#pragma unroll
        for (int ks = 0; ks < 2; ks++) {
            int kk = ks * 16;
            uint32_t a[4][4];
#pragma unroll
            for (int wm = 0; wm < 4; wm++) {
                int row = warp_m * 64 + wm * 16 + (lane & 15);
                int col = kk + ((lane >> 4) << 3);
                uint32_t addr = baseA + (uint32_t)(row * SROW + col) * 2;
                asm volatile("ldmatrix.sync.aligned.m8n8.x4.shared.b16 {%0,%1,%2,%3}, [%4];"
                             : "=r"(a[wm][0]), "=r"(a[wm][1]), "=r"(a[wm][2]), "=r"(a[wm][3])
                             : "r"(addr));
            }
            uint32_t b[8][2];
#pragma unroll
            for (int p = 0; p < 4; p++) {
                int n = warp_n * 64 + p * 16 + (lane & 7) + ((lane >> 4) << 3);
                int col = kk + (((lane >> 3) & 1) << 3);
                uint32_t addr = baseB + (uint32_t)(n * SROW + col) * 2;
                uint32_t r0, r1, r2, r3;
                asm volatile("ldmatrix.sync.aligned.m8n8.x4.shared.b16 {%0,%1,%2,%3}, [%4];"
                             : "=r"(r0), "=r"(r1), "=r"(r2), "=r"(r3) : "r"(addr));
                b[2 * p][0] = r0; b[2 * p][1] = r1;
                b[2 * p + 1][0] = r2; b[2 * p + 1][1] = r3;
            }
#pragma unroll
            for (int wm = 0; wm < 4; wm++)
#pragma unroll
                for (int wn = 0; wn < 8; wn++)
                    asm volatile(
                        "mma.sync.aligned.m16n8k16.row.col.f32.f16.f16.f32 "
                        "{%0,%1,%2,%3}, {%4,%5,%6,%7}, {%8,%9}, {%0,%1,%2,%3};"
                        : "+f"(acc[wm][wn][0]), "+f"(acc[wm][wn][1]),
                          "+f"(acc[wm][wn][2]), "+f"(acc[wm][wn][3])
                        : "r"(a[wm][0]), "r"(a[wm][1]), "r"(a[wm][2]), "r"(a[wm][3]),
                          "r"(b[wn][0]), "r"(b[wn][1]));
        }
        __syncthreads();
    }

    // Epilogue (half output only; this kernel is used for fp16-out jobs)
    __half* Ch = (__half*)j.C;
#pragma unroll
    for (int wm = 0; wm < 4; wm++) {
        int r = m0 + warp_m * 64 + wm * 16 + (lane >> 2);
#pragma unroll
        for (int wn = 0; wn < 8; wn++) {
            int c = n0 + warp_n * 64 + wn * 8 + ((lane & 3) << 1);
            float b0 = 0.f, b1 = 0.f;
            if (j.bias) { b0 = j.bias[c]; b1 = j.bias[c + 1]; }
            if (r < j.M)
                *(__half2*)(Ch + (size_t)r * j.ldc + c) =
                    __floats2half2_rn(acc[wm][wn][0] + b0, acc[wm][wn][1] + b1);
            if (r + 8 < j.M)
                *(__half2*)(Ch + (size_t)(r + 8) * j.ldc + c) =
                    __floats2half2_rn(acc[wm][wn][2] + b0, acc[wm][wn][3] + b1);
        }
    }
}

// ---------------------------------------------------------------------------
// Dual fp32->fp16 conversion (two tensors, one launch)
// ---------------------------------------------------------------------------
__global__ void tohalf2_kernel(const float4* __restrict__ x0, __half2* __restrict__ o0,
                               const float4* __restrict__ x1, __half2* __restrict__ o1,
                               int n4)
{
    int i = blockIdx.x * blockDim.x + threadIdx.x;
    const float4* x; __half2* o; int j;
    if (i < n4)          { x = x0; o = o0; j = i; }
    else if (i < 2 * n4) { x = x1; o = o1; j = i - n4; }
    else return;
    float4 v = x[j];
    o[2 * j]     = __floats2half2_rn(v.x, v.y);
    o[2 * j + 1] = __floats2half2_rn(v.z, v.w);
}

// ---------------------------------------------------------------------------
// Batched prep: 7 transposes (fp32 [KxN] -> fp16 [NxK]) + 3 bias folds + zero
// ---------------------------------------------------------------------------
__device__ __forceinline__ void tjob(const float* __restrict__ W, __half* __restrict__ T,
                                     int K, int N, int local)
{
    int k = local / N, n = local % N;
    T[(size_t)n * K + k] = __float2half(W[local]);
}
__device__ __forceinline__ void vjob(const float* __restrict__ b, const float* __restrict__ W,
                                     float* __restrict__ out, int K, int c)
{
    float a0 = 0.f, a1 = 0.f, a2 = 0.f, a3 = 0.f;
    for (int k = 0; k < K; k += 4) {
        a0 += b[k]     * W[(size_t)k * 256 + c];
        a1 += b[k + 1] * W[(size_t)(k + 1) * 256 + c];
        a2 += b[k + 2] * W[(size_t)(k + 2) * 256 + c];
        a3 += b[k + 3] * W[(size_t)(k + 3) * 256 + c];
    }
    out[c] = (a0 + a1) + (a2 + a3);
}

#define TBLOCKS 4480   // 1146880 / 256

__global__ void prep_kernel(
    const float* Wl1, const float* Wl2, const float* Wr1,
    const float* Wr2, const float* Wl3, const float* W3, const float* Wr3,
    __half* Wl1t, __half* Wl2t, __half* Wr1t,
    __half* Wr2t, __half* Wl3t, __half* W3t, __half* Wr3t,
    const float* b1, const float* b2, float* bA, float* bC)
{
    int blk = blockIdx.x;
    if (blk < TBLOCKS) {
        int t = blk * 256 + threadIdx.x;
        if      (t <  262144) tjob(Wl1, Wl1t, 1024, 256, t);
        else if (t <  524288) tjob(Wl2, Wl2t, 1024, 256, t - 262144);
        else if (t <  786432) tjob(Wr1, Wr1t, 1024, 256, t - 524288);
        else if (t <  851968) tjob(Wr2, Wr2t,  256, 256, t - 786432);
        else if (t <  917504) tjob(Wl3, Wl3t,  256, 256, t - 851968);
        else if (t <  950272) tjob(W3,  W3t,   256, 128, t - 917504);
        else                  tjob(Wr3, Wr3t,  768, 256, t - 950272);
    } else {
        int which = blk - TBLOCKS;
        int c = threadIdx.x;
        if (which == 0) vjob(b1, Wl1, bA, 1024, c);
        else if (which == 1) vjob(b1, Wl2, bA + 256, 1024, c);
        else { vjob(b2, Wr1, bC, 1024, c); bC[256 + c] = 0.f; }
    }
}

// ---------------------------------------------------------------------------
// CSR build for all 3 graphs, batched
// ---------------------------------------------------------------------------
__global__ void count3_kernel(const int* __restrict__ e0, int E0,
                              const int* __restrict__ e1, int E1,
                              const int* __restrict__ e2, int E2,
                              int* __restrict__ cnt)
{
    int t = blockIdx.x * blockDim.x + threadIdx.x;
    if (t < E0)                atomicAdd(&cnt[e0[E0 + t]], 1);
    else if (t < E0 + E1)      atomicAdd(&cnt[NROWS + e1[E1 + (t - E0)]], 1);
    else if (t < E0 + E1 + E2) atomicAdd(&cnt[2 * NROWS + e2[E2 + (t - E0 - E1)]], 1);
}

__global__ void scan3_kernel(const int* __restrict__ cnt,
                             int* __restrict__ rowstart, int* __restrict__ cursor)
{
    __shared__ int warp_sums[32];
    __shared__ int s_carry;
    int g = blockIdx.x;
    const int* c = cnt + (size_t)g * NROWS;
    int* rs = rowstart + (size_t)g * (NROWS + 1);
    int* cu = cursor + (size_t)g * NROWS;
    int tid = threadIdx.x, lane = tid & 31, wid = tid >> 5;
    if (tid == 0) s_carry = 0;
    __syncthreads();
    for (int base = 0; base < NROWS; base += 1024) {
        int i = base + tid;
        int v = (i < NROWS) ? c[i] : 0;
        int x = v;
#pragma unroll
        for (int off = 1; off < 32; off <<= 1) {
            int y = __shfl_up_sync(0xffffffffu, x, off);
            if (lane >= off) x += y;
        }
        if (lane == 31) warp_sums[wid] = x;
        __syncthreads();
        if (wid == 0) {
            int w = warp_sums[lane];
#pragma unroll
            for (int off = 1; off < 32; off <<= 1) {
                int y = __shfl_up_sync(0xffffffffu, w, off);
                if (lane >= off) w += y;
            }
            warp_sums[lane] = w;
        }
        __syncthreads();
        int warp_off = (wid > 0) ? warp_sums[wid - 1] : 0;
        int incl = x + warp_off;
        int carry = s_carry;
        if (i < NROWS) { int ex = carry + incl - v; rs[i] = ex; cu[i] = ex; }
        __syncthreads();
        if (tid == 1023) s_carry = carry + incl;
        __syncthreads();
    }
    if (tid == 0) rs[NROWS] = s_carry;
}

__global__ void fill3_kernel(const int* __restrict__ e0, int E0,
                             const int* __restrict__ e1, int E1,
                             const int* __restrict__ e2, int E2,
                             int* __restrict__ cursor, int* __restrict__ csr)
{
    int t = blockIdx.x * blockDim.x + threadIdx.x;
    if (t < E0) {
        int p = atomicAdd(&cursor[e0[E0 + t]], 1);
        csr[p] = e0[t];
    } else if (t < E0 + E1) {
        int j = t - E0;
        int p = atomicAdd(&cursor[NROWS + e1[E1 + j]], 1);
        csr[E0 + p] = e1[j];
    } else if (t < E0 + E1 + E2) {
        int j = t - E0 - E1;
        int p = atomicAdd(&cursor[2 * NROWS + e2[E2 + j]], 1);
        csr[E0 + E1 + p] = e2[j];
    }
}

// ---------------------------------------------------------------------------
// Fused mean-aggregate + bias + residual + ReLU (half2 wide, unroll-4 MLP)
// 2 rows per 256-thread block.
// out(r,:) = relu( mean_{s in row r} S[s,:] + bias + other[r,:] ), fp16 in/out
// ---------------------------------------------------------------------------
__global__ void __launch_bounds__(256)
aggregate_kernel(const int* __restrict__ rowstart, const int* __restrict__ csr,
                 const __half2* __restrict__ S2, int ldS2,
                 const __half2* __restrict__ other2, int ldO2,
                 const float* __restrict__ bias,
                 __half2* __restrict__ out2)
{
    int r = blockIdx.x * 2 + (threadIdx.x >> 7);
    int c2 = threadIdx.x & 127;
    int s = rowstart[r], e = rowstart[r + 1];
    float ax = 0.f, ay = 0.f, bx = 0.f, by = 0.f;
    int i = s;
    for (; i + 4 <= e; i += 4) {
        int i0 = csr[i], i1 = csr[i + 1], i2 = csr[i + 2], i3 = csr[i + 3];
        float2 v0 = __half22float2(S2[(size_t)i0 * ldS2 + c2]);
        float2 v1 = __half22float2(S2[(size_t)i1 * ldS2 + c2]);
        float2 v2 = __half22float2(S2[(size_t)i2 * ldS2 + c2]);
        float2 v3 = __half22float2(S2[(size_t)i3 * ldS2 + c2]);
        ax += v0.x + v1.x; ay += v0.y + v1.y;
        bx += v2.x + v3.x; by += v2.y + v3.y;
    }
    for (; i < e; i++) {
        float2 v = __half22float2(S2[(size_t)csr[i] * ldS2 + c2]);
        ax += v.x; ay += v.y;
    }
    float inv = 1.f / fmaxf((float)(e - s), 1.f);
    float2 oth = __half22float2(other2[(size_t)r * ldO2 + c2]);
    float bb0 = bias[2 * c2], bb1 = bias[2 * c2 + 1];
    float vx = fmaxf((ax + bx) * inv + bb0 + oth.x, 0.f);
    float vy = fmaxf((ay + by) * inv + bb1 + oth.y, 0.f);
    out2[(size_t)r * 128 + c2] = __floats2half2_rn(vx, vy);
}

// ---------------------------------------------------------------------------
// Host helpers  (grid: x = N-blocks [fast], y = M-blocks, z = job)
// ---------------------------------------------------------------------------
static inline void gemm1_f16(int M, int N, int K, const __half* A, const __half* B,
                             __half* C, int ldc, const float* bias)
{
    GemmJob j{A, B, (void*)C, bias, M, ldc};
    dim3 g(N / GN, (M + GM - 1) / GM, 1);
    mma_gemm_kernel<true><<<g, 256, GEMM_SMEM>>>(j, j, K);
}

extern "C" void kernel_launch(void* const* d_in, const int* in_sizes, int n_in,
                              void* d_out, int out_size)
{
    const float* article_x   = (const float*)d_in[0];
    const float* community_x = (const float*)d_in[1];
    const int*   e_wb        = (const int*)d_in[2];
    const int*   e_mb        = (const int*)d_in[3];
    const int*   e_int       = (const int*)d_in[4];
    const float* W1  = (const float*)d_in[5];
    const float* b1  = (const float*)d_in[6];
    const float* W2  = (const float*)d_in[7];
    const float* b2  = (const float*)d_in[8];
    const float* Wl1 = (const float*)d_in[9];
    const float* bl1 = (const float*)d_in[10];
    const float* Wr1 = (const float*)d_in[11];
    const float* Wl2 = (const float*)d_in[12];
    const float* bl2 = (const float*)d_in[13];
    const float* Wr2 = (const float*)d_in[14];
    const float* Wl3 = (const float*)d_in[15];
    const float* bl3 = (const float*)d_in[16];
    const float* Wr3 = (const float*)d_in[17];
    const float* W3  = (const float*)d_in[18];
    const float* b3  = (const float*)d_in[19];

    const int E0 = in_sizes[2] / 2;   // e_wb
    const int E1 = in_sizes[3] / 2;   // e_mb
    const int E2 = in_sizes[4] / 2;   // e_int

    cudaFuncSetAttribute(mma_gemm_kernel<true>,
                         cudaFuncAttributeMaxDynamicSharedMemorySize, GEMM_SMEM);
    cudaFuncSetAttribute(mma_gemm_kernel<false>,
                         cudaFuncAttributeMaxDynamicSharedMemorySize, GEMM_SMEM);
    cudaFuncSetAttribute(mma_gemm_big_kernel,
                         cudaFuncAttributeMaxDynamicSharedMemorySize, GEMM_SMEM);

    unsigned char* arena;
    cudaGetSymbolAddress((void**)&arena, g_arena);
#define AP(T, off) ((T*)(arena + (off)))
    __half *AxH  = AP(__half, OFF_AXH),  *CxH  = AP(__half, OFF_CXH);
    __half *A12H = AP(__half, OFF_A12H), *CCH  = AP(__half, OFF_CCH);
    __half *h1rH = AP(__half, OFF_H1RH), *tH   = AP(__half, OFF_TH);
    __half *h1H  = AP(__half, OFF_H1H), *h2H = AP(__half, OFF_H2H), *h3H = AP(__half, OFF_H3H);
    __half *W1H  = AP(__half, OFF_W1H), *W2H = AP(__half, OFF_W2H);
    __half *Wl1t = AP(__half, OFF_WL1T), *Wl2t = AP(__half, OFF_WL2T), *Wr1t = AP(__half, OFF_WR1T);
    __half *WAt  = AP(__half, OFF_WAT),  *WCt  = AP(__half, OFF_WCT);
    __half *Wr2t = AP(__half, OFF_WR2T), *Wl3t = AP(__half, OFF_WL3T), *W3t = AP(__half, OFF_W3T);
    float  *bA   = AP(float, OFF_BA),    *bC   = AP(float, OFF_BC);
    int *cnt = AP(int, OFF_CNT), *rowstart = AP(int, OFF_ROWST);
    int *cursor = AP(int, OFF_CURSOR), *csr = AP(int, OFF_CSR);

    // [1] W1,W2 -> fp16
    {
        int n4 = F_IN * PROJ / 4;
        tohalf2_kernel<<<(2 * n4 + 255) / 256, 256>>>(
            (const float4*)W1, (__half2*)W1H, (const float4*)W2, (__half2*)W2H, n4);
    }
    // [2] all transposes + bias folds + bC zero
    prep_kernel<<<TBLOCKS + 3, 256>>>(Wl1, Wl2, Wr1, Wr2, Wl3, W3, Wr3,
                                      Wl1t, Wl2t, Wr1t, Wr2t, Wl3t, W3t,
                                      WCt + (size_t)256 * F_IN,
                                      b1, b2, bA, bC);
    // [3] BOTH weight folds in one batched launch (z=2)
    {
        GemmJob ja{Wl1t, W1H, (void*)WAt, nullptr, 512, F_IN};
        GemmJob jc{Wr1t, W2H, (void*)WCt, nullptr, HID, F_IN};
        dim3 g(F_IN / GN, 512 / GM, 2);
        mma_gemm_kernel<true><<<g, 256, GEMM_SMEM>>>(ja, jc, PROJ);
    }
    // [4] activations -> fp16
    {
        int n4 = (int)(NR * F_IN / 4);
        tohalf2_kernel<<<(2 * n4 + 255) / 256, 256>>>(
            (const float4*)article_x, (__half2*)AxH,
            (const float4*)community_x, (__half2*)CxH, n4);
    }
    // [5] BOTH big projections, BIG-TILE kernel (4 warps, 64x64 warp tiles:
    // 33% less ldmatrix traffic on the measured L1-bound launch)
    {
        GemmJob ja{AxH, WAt, (void*)A12H, bA, NROWS, 512};
        GemmJob jc{CxH, WCt, (void*)CCH, bC, NROWS, 512};
        dim3 g(512 / GN, (NROWS + GM - 1) / GM, 2);
        mma_gemm_big_kernel<<<g, 128, GEMM_SMEM>>>(ja, jc, F_IN);
    }

    // [6-9] CSR build for all three graphs
    cudaMemsetAsync(cnt, 0, 3 * NROWS * sizeof(int));
    {
        int Etot = E0 + E1 + E2;
        count3_kernel<<<(Etot + 255) / 256, 256>>>(e_wb, E0, e_mb, E1, e_int, E2, cnt);
        scan3_kernel<<<3, 1024>>>(cnt, rowstart, cursor);
        fill3_kernel<<<(Etot + 255) / 256, 256>>>(e_wb, E0, e_mb, E1, e_int, E2, cursor, csr);
    }

    // [10] conv1: h1 = relu(mean(A1[src]) + bl1 + C1)
    aggregate_kernel<<<NROWS / 2, 256>>>(rowstart, csr,
                                         (const __half2*)A12H, 256,
                                         (const __half2*)CCH, 256, bl1, (__half2*)h1H);
    // [11] h1r = h1 @ Wr2  (fp16)
    gemm1_f16(NROWS, HID, HID, h1H, Wr2t, h1rH, HID, nullptr);
    // [12] conv2: h2 = relu(mean(A2[src]) + bl2 + h1r)
    aggregate_kernel<<<NROWS / 2, 256>>>(rowstart + (NROWS + 1), csr + E0,
                                         (const __half2*)(A12H + HID), 256,
                                         (const __half2*)h1rH, 128, bl2, (__half2*)h2H);
    // [13] t = h2 @ Wl3 (fp16: gather source)
    gemm1_f16(NROWS, HID, HID, h2H, Wl3t, tH, HID, nullptr);
    // [14] conv3: h3 = relu(mean(t[src]) + bl3 + CC[:,256:512])
    aggregate_kernel<<<NROWS / 2, 256>>>(rowstart + 2 * (NROWS + 1), csr + E0 + E1,
                                         (const __half2*)tH, 128,
                                         (const __half2*)CCH + 128, 256, bl3, (__half2*)h3H);
    // [15] out = h3 @ W3 + b3 (fp32 to d_out)
    {
        GemmJob jo{h3H, W3t, d_out, b3, NROWS, OUTD};
        dim3 g(OUTD / GN, (NROWS + GM - 1) / GM, 1);
        mma_gemm_kernel<false><<<g, 256, GEMM_SMEM>>>(jo, jo, HID);
    }
}

// round 16
// speedup vs baseline: 1.5103x; 1.0654x over previous
#include <cuda_runtime.h>
#include <cuda_fp16.h>
#include <cstdint>

// ---------------------------------------------------------------------------
// Problem constants
// ---------------------------------------------------------------------------
#define NROWS   50000
#define F_IN    768
#define PROJ    1024
#define HID     256
#define OUTD    128
#define NR ((size_t)NROWS)
#define EMAX_TOT 900000

// ---------------------------------------------------------------------------
// Arena of static device scratch (no runtime allocation allowed)
// ---------------------------------------------------------------------------
constexpr size_t OFF_AXH   = 0;                                   // half [NR x 768]
constexpr size_t OFF_CXH   = OFF_AXH + NR * F_IN * 2;             // half [NR x 768]
constexpr size_t OFF_A12H  = OFF_CXH + NR * F_IN * 2;             // half [NR x 512]
constexpr size_t OFF_CCH   = OFF_A12H + NR * 512 * 2;             // half [NR x 512]
constexpr size_t OFF_H1RH  = OFF_CCH + NR * 512 * 2;              // half [NR x 256]
constexpr size_t OFF_TH    = OFF_H1RH + NR * HID * 2;             // half [NR x 256]
constexpr size_t OFF_H1H   = OFF_TH + NR * HID * 2;
constexpr size_t OFF_H2H   = OFF_H1H + NR * HID * 2;
constexpr size_t OFF_H3H   = OFF_H2H + NR * HID * 2;
constexpr size_t OFF_W1H   = OFF_H3H + NR * HID * 2;              // half [768 x 1024]
constexpr size_t OFF_W2H   = OFF_W1H + (size_t)F_IN * PROJ * 2;
constexpr size_t OFF_WL1T  = OFF_W2H + (size_t)F_IN * PROJ * 2;   // half [256 x 1024]
constexpr size_t OFF_WL2T  = OFF_WL1T + (size_t)HID * PROJ * 2;   // contiguous after WL1T!
constexpr size_t OFF_WR1T  = OFF_WL2T + (size_t)HID * PROJ * 2;
constexpr size_t OFF_WAT   = OFF_WR1T + (size_t)HID * PROJ * 2;   // half [512 x 768]
constexpr size_t OFF_WCT   = OFF_WAT + (size_t)512 * F_IN * 2;    // half [512 x 768]
constexpr size_t OFF_WR2T  = OFF_WCT + (size_t)512 * F_IN * 2;    // half [256 x 256]
constexpr size_t OFF_WL3T  = OFF_WR2T + (size_t)HID * HID * 2;
constexpr size_t OFF_W3T   = OFF_WL3T + (size_t)HID * HID * 2;    // half [128 x 256]
constexpr size_t OFF_BA    = OFF_W3T + (size_t)OUTD * HID * 2;    // fp32 [512]
constexpr size_t OFF_BC    = OFF_BA + 512 * 4;                    // fp32 [512]
constexpr size_t OFF_CNT   = OFF_BC + 512 * 4;                    // int [3 x 50000]
constexpr size_t OFF_ROWST = OFF_CNT + 3 * NR * 4;                // int [3 x 50001]
constexpr size_t OFF_CURSOR= OFF_ROWST + 3 * (NR + 1) * 4;        // int [3 x 50000]
constexpr size_t OFF_CSR   = OFF_CURSOR + 3 * NR * 4;             // int [900000]
constexpr size_t ARENA_TOTAL = OFF_CSR + (size_t)EMAX_TOT * 4 + 64;

__device__ unsigned char g_arena[ARENA_TOTAL];

__device__ __forceinline__ uint32_t smem_u32(const void* p) {
    uint32_t a;
    asm("{ .reg .u64 t; cvta.to.shared.u64 t, %1; cvt.u32.u64 %0, t; }" : "=r"(a) : "l"(p));
    return a;
}

// ---------------------------------------------------------------------------
// Common GEMM config
// ---------------------------------------------------------------------------
#define GM 128
#define GN 128
#define GK 32
#define SROW 40
#define STAGES 3
#define ABYTES (GM * SROW * 2)            // 10240
#define STAGE_BYTES (2 * ABYTES)          // A + B per stage
#define GEMM_SMEM (STAGES * STAGE_BYTES)  // 61440

struct GemmJob {
    const __half* A;
    const __half* B;
    void* C;
    const float* bias;
    int M;
    int ldc;
};

// ---------------------------------------------------------------------------
// 8-warp GEMM (warp tile 32x64) — proven baseline, used for folds/small GEMMs.
// ---------------------------------------------------------------------------
template<bool HALF_OUT>
__global__ void __launch_bounds__(256, 2)
mma_gemm_kernel(GemmJob j0, GemmJob j1, int K)
{
    const GemmJob j = (blockIdx.z == 0) ? j0 : j1;
    const int m0 = blockIdx.y * GM;
    if (m0 >= j.M) return;
    const int n0 = blockIdx.x * GN;

    extern __shared__ __align__(16) char dynsmem[];
    const uint32_t sbase = smem_u32(dynsmem);

    const int tid = threadIdx.x;
    const int lane = tid & 31, wid = tid >> 5;
    const int warp_m = wid >> 1, warp_n = wid & 1;
    const int nk = K / GK;

    float acc[2][8][4];
#pragma unroll
    for (int i = 0; i < 2; i++)
#pragma unroll
        for (int jj = 0; jj < 8; jj++)
#pragma unroll
            for (int q = 0; q < 4; q++) acc[i][jj][q] = 0.f;

    auto issue = [&](int ch) {
        int st = ch % STAGES;
        int k0 = ch * GK;
        uint32_t baseA = sbase + st * STAGE_BYTES;
        uint32_t baseB = baseA + ABYTES;
#pragma unroll
        for (int i = 0; i < 2; i++) {
            int idx = tid + i * 256;
            int row = idx >> 2;
            int c8  = (idx & 3) << 3;
            uint32_t soff = (uint32_t)(row * SROW + c8) * 2;
            int gr = m0 + row;
            const __half* ga = j.A + (size_t)(gr < j.M ? gr : 0) * K + k0 + c8;
            int sz = (gr < j.M) ? 16 : 0;
            asm volatile("cp.async.cg.shared.global [%0], [%1], 16, %2;"
                         :: "r"(baseA + soff), "l"(ga), "r"(sz));
            const __half* gb = j.B + (size_t)(n0 + row) * K + k0 + c8;
            asm volatile("cp.async.cg.shared.global [%0], [%1], 16;"
                         :: "r"(baseB + soff), "l"(gb));
        }
        asm volatile("cp.async.commit_group;");
    };

    issue(0);
    if (nk > 1) issue(1);

    for (int ch = 0; ch < nk; ch++) {
        if (ch + 1 < nk) asm volatile("cp.async.wait_group 1;");
        else             asm volatile("cp.async.wait_group 0;");
        __syncthreads();
        if (ch + 2 < nk) issue(ch + 2);

        int st = ch % STAGES;
        uint32_t baseA = sbase + st * STAGE_BYTES;
        uint32_t baseB = baseA + ABYTES;
#pragma unroll
        for (int ks = 0; ks < 2; ks++) {
            int kk = ks * 16;
            uint32_t a[2][4];
#pragma unroll
            for (int wm = 0; wm < 2; wm++) {
                int row = warp_m * 32 + wm * 16 + (lane & 15);
                int col = kk + ((lane >> 4) << 3);
                uint32_t addr = baseA + (uint32_t)(row * SROW + col) * 2;
                asm volatile("ldmatrix.sync.aligned.m8n8.x4.shared.b16 {%0,%1,%2,%3}, [%4];"
                             : "=r"(a[wm][0]), "=r"(a[wm][1]), "=r"(a[wm][2]), "=r"(a[wm][3])
                             : "r"(addr));
            }
            uint32_t b[8][2];
#pragma unroll
            for (int p = 0; p < 4; p++) {
                int n = warp_n * 64 + p * 16 + (lane & 7) + ((lane >> 4) << 3);
                int col = kk + (((lane >> 3) & 1) << 3);
                uint32_t addr = baseB + (uint32_t)(n * SROW + col) * 2;
                uint32_t r0, r1, r2, r3;
                asm volatile("ldmatrix.sync.aligned.m8n8.x4.shared.b16 {%0,%1,%2,%3}, [%4];"
                             : "=r"(r0), "=r"(r1), "=r"(r2), "=r"(r3) : "r"(addr));
                b[2 * p][0] = r0; b[2 * p][1] = r1;
                b[2 * p + 1][0] = r2; b[2 * p + 1][1] = r3;
            }
#pragma unroll
            for (int wm = 0; wm < 2; wm++)
#pragma unroll
                for (int wn = 0; wn < 8; wn++)
                    asm volatile(
                        "mma.sync.aligned.m16n8k16.row.col.f32.f16.f16.f32 "
                        "{%0,%1,%2,%3}, {%4,%5,%6,%7}, {%8,%9}, {%0,%1,%2,%3};"
                        : "+f"(acc[wm][wn][0]), "+f"(acc[wm][wn][1]),
                          "+f"(acc[wm][wn][2]), "+f"(acc[wm][wn][3])
                        : "r"(a[wm][0]), "r"(a[wm][1]), "r"(a[wm][2]), "r"(a[wm][3]),
                          "r"(b[wn][0]), "r"(b[wn][1]));
        }
        __syncthreads();
    }

    float* Cf = (float*)j.C;
    __half* Ch = (__half*)j.C;
#pragma unroll
    for (int wm = 0; wm < 2; wm++) {
        int r = m0 + warp_m * 32 + wm * 16 + (lane >> 2);
#pragma unroll
        for (int wn = 0; wn < 8; wn++) {
            int c = n0 + warp_n * 64 + wn * 8 + ((lane & 3) << 1);
            float b0 = 0.f, b1 = 0.f;
            if (j.bias) { b0 = j.bias[c]; b1 = j.bias[c + 1]; }
            if (r < j.M) {
                float v0 = acc[wm][wn][0] + b0, v1 = acc[wm][wn][1] + b1;
                if (HALF_OUT)
                    *(__half2*)(Ch + (size_t)r * j.ldc + c) = __floats2half2_rn(v0, v1);
                else
                    *(float2*)(Cf + (size_t)r * j.ldc + c) = make_float2(v0, v1);
            }
            if (r + 8 < j.M) {
                float v0 = acc[wm][wn][2] + b0, v1 = acc[wm][wn][3] + b1;
                if (HALF_OUT)
                    *(__half2*)(Ch + (size_t)(r + 8) * j.ldc + c) = __floats2half2_rn(v0, v1);
                else
                    *(float2*)(Cf + (size_t)(r + 8) * j.ldc + c) = make_float2(v0, v1);
            }
        }
    }
}

// ---------------------------------------------------------------------------
// 4-warp BIG-TILE GEMM (warp tile 64x64) — used for the big projection launch.
// ---------------------------------------------------------------------------
__global__ void __launch_bounds__(128, 2)
mma_gemm_big_kernel(GemmJob j0, GemmJob j1, int K)
{
    const GemmJob j = (blockIdx.z == 0) ? j0 : j1;
    const int m0 = blockIdx.y * GM;
    if (m0 >= j.M) return;
    const int n0 = blockIdx.x * GN;

    extern __shared__ __align__(16) char dynsmem[];
    const uint32_t sbase = smem_u32(dynsmem);

    const int tid = threadIdx.x;
    const int lane = tid & 31, wid = tid >> 5;
    const int warp_m = wid >> 1, warp_n = wid & 1;
    const int nk = K / GK;

    float acc[4][8][4];
#pragma unroll
    for (int i = 0; i < 4; i++)
#pragma unroll
        for (int jj = 0; jj < 8; jj++)
#pragma unroll
            for (int q = 0; q < 4; q++) acc[i][jj][q] = 0.f;

    auto issue = [&](int ch) {
        int st = ch % STAGES;
        int k0 = ch * GK;
        uint32_t baseA = sbase + st * STAGE_BYTES;
        uint32_t baseB = baseA + ABYTES;
#pragma unroll
        for (int i = 0; i < 4; i++) {
            int idx = tid + i * 128;
            int row = idx >> 2;
            int c8  = (idx & 3) << 3;
            uint32_t soff = (uint32_t)(row * SROW + c8) * 2;
            int gr = m0 + row;
            const __half* ga = j.A + (size_t)(gr < j.M ? gr : 0) * K + k0 + c8;
            int sz = (gr < j.M) ? 16 : 0;
            asm volatile("cp.async.cg.shared.global [%0], [%1], 16, %2;"
                         :: "r"(baseA + soff), "l"(ga), "r"(sz));
            const __half* gb = j.B + (size_t)(n0 + row) * K + k0 + c8;
            asm volatile("cp.async.cg.shared.global [%0], [%1], 16;"
                         :: "r"(baseB + soff), "l"(gb));
        }
        asm volatile("cp.async.commit_group;");
    };

    issue(0);
    if (nk > 1) issue(1);

    for (int ch = 0; ch < nk; ch++) {
        if (ch + 1 < nk) asm volatile("cp.async.wait_group 1;");
        else             asm volatile("cp.async.wait_group 0;");
        __syncthreads();
        if (ch + 2 < nk) issue(ch + 2);

        int st = ch % STAGES;
        uint32_t baseA = sbase + st * STAGE_BYTES;
        uint32_t baseB = baseA + ABYTES;
#pragma unroll
        for (int ks = 0; ks < 2; ks++) {
            int kk = ks * 16;
            uint32_t a[4][4];
#pragma unroll
            for (int wm = 0; wm < 4; wm++) {
                int row = warp_m * 64 + wm * 16 + (lane & 15);
                int col = kk + ((lane >> 4) << 3);
                uint32_t addr = baseA + (uint32_t)(row * SROW + col) * 2;
                asm volatile("ldmatrix.sync.aligned.m8n8.x4.shared.b16 {%0,%1,%2,%3}, [%4];"
                             : "=r"(a[wm][0]), "=r"(a[wm][1]), "=r"(a[wm][2]), "=r"(a[wm][3])
                             : "r"(addr));
            }
            uint32_t b[8][2];
#pragma unroll
            for (int p = 0; p < 4; p++) {
                int n = warp_n * 64 + p * 16 + (lane & 7) + ((lane >> 4) << 3);
                int col = kk + (((lane >> 3) & 1) << 3);
                uint32_t addr = baseB + (uint32_t)(n * SROW + col) * 2;
                uint32_t r0, r1, r2, r3;
                asm volatile("ldmatrix.sync.aligned.m8n8.x4.shared.b16 {%0,%1,%2,%3}, [%4];"
                             : "=r"(r0), "=r"(r1), "=r"(r2), "=r"(r3) : "r"(addr));
                b[2 * p][0] = r0; b[2 * p][1] = r1;
                b[2 * p + 1][0] = r2; b[2 * p + 1][1] = r3;
            }
#pragma unroll
            for (int wm = 0; wm < 4; wm++)
#pragma unroll
                for (int wn = 0; wn < 8; wn++)
                    asm volatile(
                        "mma.sync.aligned.m16n8k16.row.col.f32.f16.f16.f32 "
                        "{%0,%1,%2,%3}, {%4,%5,%6,%7}, {%8,%9}, {%0,%1,%2,%3};"
                        : "+f"(acc[wm][wn][0]), "+f"(acc[wm][wn][1]),
                          "+f"(acc[wm][wn][2]), "+f"(acc[wm][wn][3])
                        : "r"(a[wm][0]), "r"(a[wm][1]), "r"(a[wm][2]), "r"(a[wm][3]),
                          "r"(b[wn][0]), "r"(b[wn][1]));
        }
        __syncthreads();
    }

    __half* Ch = (__half*)j.C;
#pragma unroll
    for (int wm = 0; wm < 4; wm++) {
        int r = m0 + warp_m * 64 + wm * 16 + (lane >> 2);
#pragma unroll
        for (int wn = 0; wn < 8; wn++) {
            int c = n0 + warp_n * 64 + wn * 8 + ((lane & 3) << 1);
            float b0 = 0.f, b1 = 0.f;
            if (j.bias) { b0 = j.bias[c]; b1 = j.bias[c + 1]; }
            if (r < j.M)
                *(__half2*)(Ch + (size_t)r * j.ldc + c) =
                    __floats2half2_rn(acc[wm][wn][0] + b0, acc[wm][wn][1] + b1);
            if (r + 8 < j.M)
                *(__half2*)(Ch + (size_t)(r + 8) * j.ldc + c) =
                    __floats2half2_rn(acc[wm][wn][2] + b0, acc[wm][wn][3] + b1);
        }
    }
}

// ---------------------------------------------------------------------------
// Dual fp32->fp16 conversion (two tensors, one launch)
// ---------------------------------------------------------------------------
__global__ void tohalf2_kernel(const float4* __restrict__ x0, __half2* __restrict__ o0,
                               const float4* __restrict__ x1, __half2* __restrict__ o1,
                               int n4)
{
    int i = blockIdx.x * blockDim.x + threadIdx.x;
    const float4* x; __half2* o; int j;
    if (i < n4)          { x = x0; o = o0; j = i; }
    else if (i < 2 * n4) { x = x1; o = o1; j = i - n4; }
    else return;
    float4 v = x[j];
    o[2 * j]     = __floats2half2_rn(v.x, v.y);
    o[2 * j + 1] = __floats2half2_rn(v.z, v.w);
}

// ---------------------------------------------------------------------------
// Batched prep: 7 transposes + 3 bias folds + zero
// ---------------------------------------------------------------------------
__device__ __forceinline__ void tjob(const float* __restrict__ W, __half* __restrict__ T,
                                     int K, int N, int local)
{
    int k = local / N, n = local % N;
    T[(size_t)n * K + k] = __float2half(W[local]);
}
__device__ __forceinline__ void vjob(const float* __restrict__ b, const float* __restrict__ W,
                                     float* __restrict__ out, int K, int c)
{
    float a0 = 0.f, a1 = 0.f, a2 = 0.f, a3 = 0.f;
    for (int k = 0; k < K; k += 4) {
        a0 += b[k]     * W[(size_t)k * 256 + c];
        a1 += b[k + 1] * W[(size_t)(k + 1) * 256 + c];
        a2 += b[k + 2] * W[(size_t)(k + 2) * 256 + c];
        a3 += b[k + 3] * W[(size_t)(k + 3) * 256 + c];
    }
    out[c] = (a0 + a1) + (a2 + a3);
}

#define TBLOCKS 4480   // 1146880 / 256

__global__ void prep_kernel(
    const float* Wl1, const float* Wl2, const float* Wr1,
    const float* Wr2, const float* Wl3, const float* W3, const float* Wr3,
    __half* Wl1t, __half* Wl2t, __half* Wr1t,
    __half* Wr2t, __half* Wl3t, __half* W3t, __half* Wr3t,
    const float* b1, const float* b2, float* bA, float* bC)
{
    int blk = blockIdx.x;
    if (blk < TBLOCKS) {
        int t = blk * 256 + threadIdx.x;
        if      (t <  262144) tjob(Wl1, Wl1t, 1024, 256, t);
        else if (t <  524288) tjob(Wl2, Wl2t, 1024, 256, t - 262144);
        else if (t <  786432) tjob(Wr1, Wr1t, 1024, 256, t - 524288);
        else if (t <  851968) tjob(Wr2, Wr2t,  256, 256, t - 786432);
        else if (t <  917504) tjob(Wl3, Wl3t,  256, 256, t - 851968);
        else if (t <  950272) tjob(W3,  W3t,   256, 128, t - 917504);
        else                  tjob(Wr3, Wr3t,  768, 256, t - 950272);
    } else {
        int which = blk - TBLOCKS;
        int c = threadIdx.x;
        if (which == 0) vjob(b1, Wl1, bA, 1024, c);
        else if (which == 1) vjob(b1, Wl2, bA + 256, 1024, c);
        else { vjob(b2, Wr1, bC, 1024, c); bC[256 + c] = 0.f; }
    }
}

// ---------------------------------------------------------------------------
// CSR build for all 3 graphs, batched
// ---------------------------------------------------------------------------
__global__ void count3_kernel(const int* __restrict__ e0, int E0,
                              const int* __restrict__ e1, int E1,
                              const int* __restrict__ e2, int E2,
                              int* __restrict__ cnt)
{
    int t = blockIdx.x * blockDim.x + threadIdx.x;
    if (t < E0)                atomicAdd(&cnt[e0[E0 + t]], 1);
    else if (t < E0 + E1)      atomicAdd(&cnt[NROWS + e1[E1 + (t - E0)]], 1);
    else if (t < E0 + E1 + E2) atomicAdd(&cnt[2 * NROWS + e2[E2 + (t - E0 - E1)]], 1);
}

__global__ void scan3_kernel(const int* __restrict__ cnt,
                             int* __restrict__ rowstart, int* __restrict__ cursor)
{
    __shared__ int warp_sums[32];
    __shared__ int s_carry;
    int g = blockIdx.x;
    const int* c = cnt + (size_t)g * NROWS;
    int* rs = rowstart + (size_t)g * (NROWS + 1);
    int* cu = cursor + (size_t)g * NROWS;
    int tid = threadIdx.x, lane = tid & 31, wid = tid >> 5;
    if (tid == 0) s_carry = 0;
    __syncthreads();
    for (int base = 0; base < NROWS; base += 1024) {
        int i = base + tid;
        int v = (i < NROWS) ? c[i] : 0;
        int x = v;
#pragma unroll
        for (int off = 1; off < 32; off <<= 1) {
            int y = __shfl_up_sync(0xffffffffu, x, off);
            if (lane >= off) x += y;
        }
        if (lane == 31) warp_sums[wid] = x;
        __syncthreads();
        if (wid == 0) {
            int w = warp_sums[lane];
#pragma unroll
            for (int off = 1; off < 32; off <<= 1) {
                int y = __shfl_up_sync(0xffffffffu, w, off);
                if (lane >= off) w += y;
            }
            warp_sums[lane] = w;
        }
        __syncthreads();
        int warp_off = (wid > 0) ? warp_sums[wid - 1] : 0;
        int incl = x + warp_off;
        int carry = s_carry;
        if (i < NROWS) { int ex = carry + incl - v; rs[i] = ex; cu[i] = ex; }
        __syncthreads();
        if (tid == 1023) s_carry = carry + incl;
        __syncthreads();
    }
    if (tid == 0) rs[NROWS] = s_carry;
}

__global__ void fill3_kernel(const int* __restrict__ e0, int E0,
                             const int* __restrict__ e1, int E1,
                             const int* __restrict__ e2, int E2,
                             int* __restrict__ cursor, int* __restrict__ csr)
{
    int t = blockIdx.x * blockDim.x + threadIdx.x;
    if (t < E0) {
        int p = atomicAdd(&cursor[e0[E0 + t]], 1);
        csr[p] = e0[t];
    } else if (t < E0 + E1) {
        int j = t - E0;
        int p = atomicAdd(&cursor[NROWS + e1[E1 + j]], 1);
        csr[E0 + p] = e1[j];
    } else if (t < E0 + E1 + E2) {
        int j = t - E0 - E1;
        int p = atomicAdd(&cursor[2 * NROWS + e2[E2 + j]], 1);
        csr[E0 + E1 + p] = e2[j];
    }
}

// ---------------------------------------------------------------------------
// Fused mean-aggregate + bias + residual + ReLU (2 rows / 256-thread block)
// ---------------------------------------------------------------------------
__global__ void __launch_bounds__(256)
aggregate_kernel(const int* __restrict__ rowstart, const int* __restrict__ csr,
                 const __half2* __restrict__ S2, int ldS2,
                 const __half2* __restrict__ other2, int ldO2,
                 const float* __restrict__ bias,
                 __half2* __restrict__ out2)
{
    int r = blockIdx.x * 2 + (threadIdx.x >> 7);
    int c2 = threadIdx.x & 127;
    int s = rowstart[r], e = rowstart[r + 1];
    float ax = 0.f, ay = 0.f, bx = 0.f, by = 0.f;
    int i = s;
    for (; i + 4 <= e; i += 4) {
        int i0 = csr[i], i1 = csr[i + 1], i2 = csr[i + 2], i3 = csr[i + 3];
        float2 v0 = __half22float2(S2[(size_t)i0 * ldS2 + c2]);
        float2 v1 = __half22float2(S2[(size_t)i1 * ldS2 + c2]);
        float2 v2 = __half22float2(S2[(size_t)i2 * ldS2 + c2]);
        float2 v3 = __half22float2(S2[(size_t)i3 * ldS2 + c2]);
        ax += v0.x + v1.x; ay += v0.y + v1.y;
        bx += v2.x + v3.x; by += v2.y + v3.y;
    }
    for (; i < e; i++) {
        float2 v = __half22float2(S2[(size_t)csr[i] * ldS2 + c2]);
        ax += v.x; ay += v.y;
    }
    float inv = 1.f / fmaxf((float)(e - s), 1.f);
    float2 oth = __half22float2(other2[(size_t)r * ldO2 + c2]);
    float bb0 = bias[2 * c2], bb1 = bias[2 * c2 + 1];
    float vx = fmaxf((ax + bx) * inv + bb0 + oth.x, 0.f);
    float vy = fmaxf((ay + by) * inv + bb1 + oth.y, 0.f);
    out2[(size_t)r * 128 + c2] = __floats2half2_rn(vx, vy);
}

// ---------------------------------------------------------------------------
// Host helpers  (grid: x = N-blocks [fast], y = M-blocks, z = job)
// ---------------------------------------------------------------------------
static inline void gemm1_f16(int M, int N, int K, const __half* A, const __half* B,
                             __half* C, int ldc, const float* bias)
{
    GemmJob j{A, B, (void*)C, bias, M, ldc};
    dim3 g(N / GN, (M + GM - 1) / GM, 1);
    mma_gemm_kernel<true><<<g, 256, GEMM_SMEM>>>(j, j, K);
}

extern "C" void kernel_launch(void* const* d_in, const int* in_sizes, int n_in,
                              void* d_out, int out_size)
{
    const float* article_x   = (const float*)d_in[0];
    const float* community_x = (const float*)d_in[1];
    const int*   e_wb        = (const int*)d_in[2];
    const int*   e_mb        = (const int*)d_in[3];
    const int*   e_int       = (const int*)d_in[4];
    const float* W1  = (const float*)d_in[5];
    const float* b1  = (const float*)d_in[6];
    const float* W2  = (const float*)d_in[7];
    const float* b2  = (const float*)d_in[8];
    const float* Wl1 = (const float*)d_in[9];
    const float* bl1 = (const float*)d_in[10];
    const float* Wr1 = (const float*)d_in[11];
    const float* Wl2 = (const float*)d_in[12];
    const float* bl2 = (const float*)d_in[13];
    const float* Wr2 = (const float*)d_in[14];
    const float* Wl3 = (const float*)d_in[15];
    const float* bl3 = (const float*)d_in[16];
    const float* Wr3 = (const float*)d_in[17];
    const float* W3  = (const float*)d_in[18];
    const float* b3  = (const float*)d_in[19];

    const int E0 = in_sizes[2] / 2;
    const int E1 = in_sizes[3] / 2;
    const int E2 = in_sizes[4] / 2;

    cudaFuncSetAttribute(mma_gemm_kernel<true>,
                         cudaFuncAttributeMaxDynamicSharedMemorySize, GEMM_SMEM);
    cudaFuncSetAttribute(mma_gemm_kernel<false>,
                         cudaFuncAttributeMaxDynamicSharedMemorySize, GEMM_SMEM);
    cudaFuncSetAttribute(mma_gemm_big_kernel,
                         cudaFuncAttributeMaxDynamicSharedMemorySize, GEMM_SMEM);

    // Side streams + events, created once on the first (uncaptured) call.
    static cudaStream_t sW = nullptr, sCsr = nullptr;
    static cudaEvent_t evRoot = nullptr, evW = nullptr, evCsr = nullptr;
    if (sW == nullptr) {
        cudaStreamCreateWithFlags(&sW, cudaStreamNonBlocking);
        cudaStreamCreateWithFlags(&sCsr, cudaStreamNonBlocking);
        cudaEventCreateWithFlags(&evRoot, cudaEventDisableTiming);
        cudaEventCreateWithFlags(&evW, cudaEventDisableTiming);
        cudaEventCreateWithFlags(&evCsr, cudaEventDisableTiming);
    }

    unsigned char* arena;
    cudaGetSymbolAddress((void**)&arena, g_arena);
#define AP(T, off) ((T*)(arena + (off)))
    __half *AxH  = AP(__half, OFF_AXH),  *CxH  = AP(__half, OFF_CXH);
    __half *A12H = AP(__half, OFF_A12H), *CCH  = AP(__half, OFF_CCH);
    __half *h1rH = AP(__half, OFF_H1RH), *tH   = AP(__half, OFF_TH);
    __half *h1H  = AP(__half, OFF_H1H), *h2H = AP(__half, OFF_H2H), *h3H = AP(__half, OFF_H3H);
    __half *W1H  = AP(__half, OFF_W1H), *W2H = AP(__half, OFF_W2H);
    __half *Wl1t = AP(__half, OFF_WL1T), *Wl2t = AP(__half, OFF_WL2T), *Wr1t = AP(__half, OFF_WR1T);
    __half *WAt  = AP(__half, OFF_WAT),  *WCt  = AP(__half, OFF_WCT);
    __half *Wr2t = AP(__half, OFF_WR2T), *Wl3t = AP(__half, OFF_WL3T), *W3t = AP(__half, OFF_W3T);
    float  *bA   = AP(float, OFF_BA),    *bC   = AP(float, OFF_BC);
    int *cnt = AP(int, OFF_CNT), *rowstart = AP(int, OFF_ROWST);
    int *cursor = AP(int, OFF_CURSOR), *csr = AP(int, OFF_CSR);

    // ---- fork: root event on the main (capture) stream ----
    cudaEventRecord(evRoot, 0);

    // ---- side stream W: weight chain [1][2][3] ----
    cudaStreamWaitEvent(sW, evRoot, 0);
    {
        int n4 = F_IN * PROJ / 4;
        tohalf2_kernel<<<(2 * n4 + 255) / 256, 256, 0, sW>>>(
            (const float4*)W1, (__half2*)W1H, (const float4*)W2, (__half2*)W2H, n4);
    }
    prep_kernel<<<TBLOCKS + 3, 256, 0, sW>>>(Wl1, Wl2, Wr1, Wr2, Wl3, W3, Wr3,
                                             Wl1t, Wl2t, Wr1t, Wr2t, Wl3t, W3t,
                                             WCt + (size_t)256 * F_IN,
                                             b1, b2, bA, bC);
    {
        GemmJob ja{Wl1t, W1H, (void*)WAt, nullptr, 512, F_IN};
        GemmJob jc{Wr1t, W2H, (void*)WCt, nullptr, HID, F_IN};
        dim3 g(F_IN / GN, 512 / GM, 2);
        mma_gemm_kernel<true><<<g, 256, GEMM_SMEM, sW>>>(ja, jc, PROJ);
    }
    cudaEventRecord(evW, sW);

    // ---- side stream CSR: graph build (independent until conv1) ----
    cudaStreamWaitEvent(sCsr, evRoot, 0);
    cudaMemsetAsync(cnt, 0, 3 * NROWS * sizeof(int), sCsr);
    {
        int Etot = E0 + E1 + E2;
        count3_kernel<<<(Etot + 255) / 256, 256, 0, sCsr>>>(e_wb, E0, e_mb, E1, e_int, E2, cnt);
        scan3_kernel<<<3, 1024, 0, sCsr>>>(cnt, rowstart, cursor);
        fill3_kernel<<<(Etot + 255) / 256, 256, 0, sCsr>>>(e_wb, E0, e_mb, E1, e_int, E2, cursor, csr);
    }
    cudaEventRecord(evCsr, sCsr);

    // ---- main stream: activation conversion (overlaps weight chain) ----
    {
        int n4 = (int)(NR * F_IN / 4);
        tohalf2_kernel<<<(2 * n4 + 255) / 256, 256>>>(
            (const float4*)article_x, (__half2*)AxH,
            (const float4*)community_x, (__half2*)CxH, n4);
    }

    // ---- join W, then big projections (CSR chain overlaps these) ----
    cudaStreamWaitEvent(0, evW, 0);
    {
        GemmJob ja{AxH, WAt, (void*)A12H, bA, NROWS, 512};
        GemmJob jc{CxH, WCt, (void*)CCH, bC, NROWS, 512};
        dim3 g(512 / GN, (NROWS + GM - 1) / GM, 2);
        mma_gemm_big_kernel<<<g, 128, GEMM_SMEM>>>(ja, jc, F_IN);
    }

    // ---- join CSR, then conv stages ----
    cudaStreamWaitEvent(0, evCsr, 0);

    aggregate_kernel<<<NROWS / 2, 256>>>(rowstart, csr,
                                         (const __half2*)A12H, 256,
                                         (const __half2*)CCH, 256, bl1, (__half2*)h1H);
    gemm1_f16(NROWS, HID, HID, h1H, Wr2t, h1rH, HID, nullptr);
    aggregate_kernel<<<NROWS / 2, 256>>>(rowstart + (NROWS + 1), csr + E0,
                                         (const __half2*)(A12H + HID), 256,
                                         (const __half2*)h1rH, 128, bl2, (__half2*)h2H);
    gemm1_f16(NROWS, HID, HID, h2H, Wl3t, tH, HID, nullptr);
    aggregate_kernel<<<NROWS / 2, 256>>>(rowstart + 2 * (NROWS + 1), csr + E0 + E1,
                                         (const __half2*)tH, 128,
                                         (const __half2*)CCH + 128, 256, bl3, (__half2*)h3H);
    {
        GemmJob jo{h3H, W3t, d_out, b3, NROWS, OUTD};
        dim3 g(OUTD / GN, (NROWS + GM - 1) / GM, 1);
        mma_gemm_kernel<false><<<g, 256, GEMM_SMEM>>>(jo, jo, HID);
    }
}